// round 1
// baseline (speedup 1.0000x reference)
#include <cuda_runtime.h>

// ---------------------------------------------------------------------------
// Problem constants (shapes are fixed by the dataset: B=16, N=E=4096, dims 512)
// ---------------------------------------------------------------------------
#define MROWS   65536          // B*N total node rows
#define DFEAT   512            // FIN == HID == OUT
#define NEDGES  65536          // B*E

// Scratch (allocation-free: __device__ globals)
__device__ float g_support[(size_t)MROWS * DFEAT];   // GEMM output / messages
__device__ float g_h1[(size_t)MROWS * DFEAT];        // conv1 pre-relu output
__device__ float g_h2[(size_t)MROWS * DFEAT];        // conv2 pre-relu output
__device__ float g_z[(size_t)MROWS * 2 * DFEAT];     // concat buffer (reused)

// ---------------------------------------------------------------------------
// SGEMM: C[M,N] = A[M,K] @ B[K,N]  (+ optional bias & leaky-relu epilogue)
// 128x128 block tile, BK=8, 256 threads, 8x8 per thread. All dims are exact
// multiples of the tiles for this problem, so no bounds checks.
// ---------------------------------------------------------------------------
#define BM 128
#define BN 128
#define BK 8
#define TM 8
#define TN 8

template<int EPI>   // 0 = plain store, 1 = +bias then leaky_relu(0.01)
__global__ __launch_bounds__(256)
void sgemm_kernel(const float* __restrict__ A, const float* __restrict__ Bm,
                  float* __restrict__ C, int M, int N, int K,
                  const float* __restrict__ bias)
{
    __shared__ __align__(16) float As[BK][BM];
    __shared__ __align__(16) float Bs[BK][BN];

    const int tid  = threadIdx.x;
    const int trow = (tid >> 4) * TM;       // 0..120
    const int tcol = (tid & 15) * TN;       // 0..120
    const long bm  = (long)blockIdx.y * BM;
    const long bn  = (long)blockIdx.x * BN;

    // A tile (128 rows x 8 cols): one float4 per thread
    const int a_row = tid >> 1;             // 0..127
    const int a_col = (tid & 1) * 4;        // 0 or 4
    // B tile (8 rows x 128 cols): one float4 per thread
    const int b_row = tid >> 5;             // 0..7
    const int b_col = (tid & 31) * 4;       // 0..124

    const float* Aptr = A + (bm + a_row) * (long)K + a_col;
    const float* Bptr = Bm + (long)b_row * N + bn + b_col;

    float acc[TM][TN];
#pragma unroll
    for (int i = 0; i < TM; i++)
#pragma unroll
        for (int j = 0; j < TN; j++) acc[i][j] = 0.0f;

    for (int k0 = 0; k0 < K; k0 += BK) {
        float4 av = *(const float4*)(Aptr + k0);
        As[a_col + 0][a_row] = av.x;
        As[a_col + 1][a_row] = av.y;
        As[a_col + 2][a_row] = av.z;
        As[a_col + 3][a_row] = av.w;
        *(float4*)&Bs[b_row][b_col] = *(const float4*)(Bptr + (long)k0 * N);
        __syncthreads();

#pragma unroll
        for (int k = 0; k < BK; k++) {
            float4 a0 = *(const float4*)&As[k][trow];
            float4 a1 = *(const float4*)&As[k][trow + 4];
            float4 b0 = *(const float4*)&Bs[k][tcol];
            float4 b1 = *(const float4*)&Bs[k][tcol + 4];
            float af[TM] = {a0.x, a0.y, a0.z, a0.w, a1.x, a1.y, a1.z, a1.w};
            float bf[TN] = {b0.x, b0.y, b0.z, b0.w, b1.x, b1.y, b1.z, b1.w};
#pragma unroll
            for (int i = 0; i < TM; i++)
#pragma unroll
                for (int j = 0; j < TN; j++)
                    acc[i][j] += af[i] * bf[j];
        }
        __syncthreads();
    }

#pragma unroll
    for (int i = 0; i < TM; i++) {
        float* crow = C + (bm + trow + i) * (long)N + bn + tcol;
#pragma unroll
        for (int j = 0; j < TN; j += 4) {
            float4 v;
            v.x = acc[i][j + 0];
            v.y = acc[i][j + 1];
            v.z = acc[i][j + 2];
            v.w = acc[i][j + 3];
            if (EPI == 1) {
                const float* bptr = bias + bn + tcol + j;
                v.x += bptr[0]; v.y += bptr[1]; v.z += bptr[2]; v.w += bptr[3];
                v.x = (v.x >= 0.f) ? v.x : 0.01f * v.x;
                v.y = (v.y >= 0.f) ? v.y : 0.01f * v.y;
                v.z = (v.z >= 0.f) ? v.z : 0.01f * v.z;
                v.w = (v.w >= 0.f) ? v.w : 0.01f * v.w;
            }
            *(float4*)(crow + j) = v;
        }
    }
}

// ---------------------------------------------------------------------------
// init rows to the bias vector: out[i, j] = bias[j]
// ---------------------------------------------------------------------------
__global__ void init_bias_kernel(float* __restrict__ out,
                                 const float* __restrict__ bias)
{
    long idx = (long)blockIdx.x * blockDim.x + threadIdx.x;      // float4 index
    long total = (long)MROWS * (DFEAT / 4);
    if (idx >= total) return;
    int j4 = (int)(idx & (DFEAT / 4 - 1));
    ((float4*)out)[idx] = ((const float4*)bias)[j4];
}

// ---------------------------------------------------------------------------
// Edge scatter: dst[row[e], :] += w[e] * src[col[e], :]   (one warp per edge)
// ---------------------------------------------------------------------------
__global__ void scatter_kernel(const float* __restrict__ src,
                               const int* __restrict__ rows,
                               const int* __restrict__ cols,
                               const float* __restrict__ vals,
                               float* __restrict__ dst, int nE)
{
    int e = blockIdx.x * 8 + (threadIdx.x >> 5);
    if (e >= nE) return;
    int lane = threadIdx.x & 31;
    int r = rows[e];
    int c = cols[e];
    float w = vals[e];
    const float4* s = (const float4*)(src + (long)c * DFEAT);
    float* d = dst + (long)r * DFEAT;
#pragma unroll
    for (int j = lane; j < DFEAT / 4; j += 32) {
        float4 v = s[j];
        atomicAdd(d + 4 * j + 0, w * v.x);
        atomicAdd(d + 4 * j + 1, w * v.y);
        atomicAdd(d + 4 * j + 2, w * v.z);
        atomicAdd(d + 4 * j + 3, w * v.w);
    }
}

// ---------------------------------------------------------------------------
// z = [relu(h1) | relu(features[root])]   (rows: MROWS, width 1024)
// ---------------------------------------------------------------------------
__global__ void build_z_kernel(const float* __restrict__ h1,
                               const float* __restrict__ feat,
                               const int* __restrict__ root_idx,
                               float* __restrict__ z, int nper)
{
    long idx = (long)blockIdx.x * blockDim.x + threadIdx.x;      // float4 index
    long total = (long)MROWS * (DFEAT / 4);
    if (idx >= total) return;
    long r = idx >> 7;                  // DFEAT/4 == 128
    int j4 = (int)(idx & 127);
    int root = root_idx[(int)(r / nper)];

    float4 h = ((const float4*)h1)[r * 128 + j4];
    float4 f = ((const float4*)feat)[(long)root * 128 + j4];
    h.x = fmaxf(h.x, 0.f); h.y = fmaxf(h.y, 0.f);
    h.z = fmaxf(h.z, 0.f); h.w = fmaxf(h.w, 0.f);
    f.x = fmaxf(f.x, 0.f); f.y = fmaxf(f.y, 0.f);
    f.z = fmaxf(f.z, 0.f); f.w = fmaxf(f.w, 0.f);

    float4* zr = ((float4*)z) + r * 256;
    zr[j4]       = h;
    zr[128 + j4] = f;
}

// ---------------------------------------------------------------------------
// c2 = [relu(h2pre) | h1[root]]   (rows: MROWS, width 1024)
// ---------------------------------------------------------------------------
__global__ void build_c2_kernel(const float* __restrict__ h2,
                                const float* __restrict__ h1,
                                const int* __restrict__ root_idx,
                                float* __restrict__ c2, int nper)
{
    long idx = (long)blockIdx.x * blockDim.x + threadIdx.x;
    long total = (long)MROWS * (DFEAT / 4);
    if (idx >= total) return;
    long r = idx >> 7;
    int j4 = (int)(idx & 127);
    int root = root_idx[(int)(r / nper)];

    float4 h = ((const float4*)h2)[r * 128 + j4];
    float4 g = ((const float4*)h1)[(long)root * 128 + j4];
    h.x = fmaxf(h.x, 0.f); h.y = fmaxf(h.y, 0.f);
    h.z = fmaxf(h.z, 0.f); h.w = fmaxf(h.w, 0.f);

    float4* cr = ((float4*)c2) + r * 256;
    cr[j4]       = h;
    cr[128 + j4] = g;   // pre-relu h1, per reference
}

// ---------------------------------------------------------------------------
// launch
// ---------------------------------------------------------------------------
extern "C" void kernel_launch(void* const* d_in, const int* in_sizes, int n_in,
                              void* d_out, int out_size)
{
    const float* features = (const float*)d_in[0];
    const int*   adjs     = (const int*)  d_in[1];
    const float* values   = (const float*)d_in[2];
    const int*   root_idx = (const int*)  d_in[3];
    // d_in[4], d_in[5]: node/edge counts (constant for this problem)
    const float* W1 = (const float*)d_in[6];
    const float* b1 = (const float*)d_in[7];
    const float* W2 = (const float*)d_in[8];
    const float* b2 = (const float*)d_in[9];
    const float* Wl = (const float*)d_in[10];
    const float* bl = (const float*)d_in[11];
    float* out = (float*)d_out;

    const int nE   = in_sizes[2];            // 65536
    const int Bg   = in_sizes[3];            // 16
    const int nper = (in_sizes[0] / DFEAT) / Bg;  // 4096

    float *support, *h1, *h2, *z;
    cudaGetSymbolAddress((void**)&support, g_support);
    cudaGetSymbolAddress((void**)&h1,      g_h1);
    cudaGetSymbolAddress((void**)&h2,      g_h2);
    cudaGetSymbolAddress((void**)&z,       g_z);

    const int* rows = adjs;         // global src indices
    const int* cols = adjs + nE;    // global dst indices

    dim3 gemm_grid(DFEAT / BN, MROWS / BM);     // (4, 512)
    const long ew_total = (long)MROWS * (DFEAT / 4);
    const int  ew_blocks = (int)((ew_total + 255) / 256);
    const int  sc_blocks = (nE + 7) / 8;

    // 1) support1 = X @ W1
    sgemm_kernel<0><<<gemm_grid, 256>>>(features, W1, support,
                                        MROWS, DFEAT, DFEAT, nullptr);
    // 2) h1 = b1; h1[row] += w * support1[col]
    init_bias_kernel<<<ew_blocks, 256>>>(h1, b1);
    scatter_kernel<<<sc_blocks, 256>>>(support, rows, cols, values, h1, nE);
    // 3) z = [relu(h1) | relu(x[root])]
    build_z_kernel<<<ew_blocks, 256>>>(h1, features, root_idx, z, nper);
    // 4) support2 = z @ W2
    sgemm_kernel<0><<<gemm_grid, 256>>>(z, W2, support,
                                        MROWS, DFEAT, 2 * DFEAT, nullptr);
    // 5) h2pre = b2; h2pre[row] += w * support2[col]
    init_bias_kernel<<<ew_blocks, 256>>>(h2, b2);
    scatter_kernel<<<sc_blocks, 256>>>(support, rows, cols, values, h2, nE);
    // 6) c2 = [relu(h2pre) | h1[root]]
    build_c2_kernel<<<ew_blocks, 256>>>(h2, h1, root_idx, z, nper);
    // 7) out = leaky_relu(c2 @ Wl + bl)
    sgemm_kernel<1><<<gemm_grid, 256>>>(z, Wl, out,
                                        MROWS, DFEAT, 2 * DFEAT, bl);
}

// round 3
// speedup vs baseline: 2.0784x; 2.0784x over previous
#include <cuda_runtime.h>
#include <cuda_bf16.h>
#include <cstdint>

#define MROWS   65536
#define DFEAT   512
#define NEDGES  65536

// ---------------------------------------------------------------------------
// Scratch (__device__ globals; allocation-free)
// ---------------------------------------------------------------------------
__device__ float g_support[(size_t)MROWS * DFEAT];
__device__ float g_h1[(size_t)MROWS * DFEAT];
__device__ float g_h2[(size_t)MROWS * DFEAT];
__device__ __nv_bfloat16 g_ah[(size_t)MROWS * 1024];   // A-hi (feat / z / c2)
__device__ __nv_bfloat16 g_al[(size_t)MROWS * 1024];   // A-lo
__device__ __nv_bfloat16 g_w1h[512 * 512],  g_w1l[512 * 512];
__device__ __nv_bfloat16 g_w2h[512 * 1024], g_w2l[512 * 1024];
__device__ __nv_bfloat16 g_wlh[512 * 1024], g_wll[512 * 1024];

// ---------------------------------------------------------------------------
// PTX helpers (cp.async / ldmatrix / mma.sync — all plain sm_80+ PTX)
// ---------------------------------------------------------------------------
__device__ __forceinline__ uint32_t smem_u32(const void* p) {
    return (uint32_t)__cvta_generic_to_shared(p);
}
__device__ __forceinline__ void cp_async16(uint32_t dst, const void* src) {
    asm volatile("cp.async.cg.shared.global [%0], [%1], 16;" :: "r"(dst), "l"(src));
}
__device__ __forceinline__ void cp_commit() {
    asm volatile("cp.async.commit_group;");
}
template<int N>
__device__ __forceinline__ void cp_wait() {
    asm volatile("cp.async.wait_group %0;" :: "n"(N));
}
__device__ __forceinline__ void ldsm_x4(uint32_t& r0, uint32_t& r1,
                                        uint32_t& r2, uint32_t& r3, uint32_t a) {
    asm volatile("ldmatrix.sync.aligned.m8n8.x4.shared.b16 {%0,%1,%2,%3}, [%4];"
                 : "=r"(r0), "=r"(r1), "=r"(r2), "=r"(r3) : "r"(a));
}
__device__ __forceinline__ void mma16816(float* c, const uint32_t* a, const uint32_t* b) {
    asm volatile(
        "mma.sync.aligned.m16n8k16.row.col.f32.bf16.bf16.f32 "
        "{%0,%1,%2,%3}, {%4,%5,%6,%7}, {%8,%9}, {%0,%1,%2,%3};"
        : "+f"(c[0]), "+f"(c[1]), "+f"(c[2]), "+f"(c[3])
        : "r"(a[0]), "r"(a[1]), "r"(a[2]), "r"(a[3]), "r"(b[0]), "r"(b[1]));
}

// ---------------------------------------------------------------------------
// bf16x3 split GEMM on tensor cores (mma.sync):
//   C[M,512] = (Ah+Al)[M,K] @ (Bh+Bl)[512,K]^T   (drop Al@Bl)
// CTA tile 128x256, 512 threads (4x4 warps, warp tile 32x64), BK=64,
// 3-stage cp.async pipeline, SW128-swizzled smem, ldmatrix fragments.
// ---------------------------------------------------------------------------
#define BM2 128
#define BN2 256
#define BK2 64
#define NSTAGE 3
#define SMA (BM2 * 128)            // 16 KB (128B per row)
#define SMB (BN2 * 128)            // 32 KB
#define SMSTAGE (SMA + SMB)        // 48 KB
#define SMTOTAL (NSTAGE * SMSTAGE + 1024)

template<int EPI>   // 0 = plain fp32 store; 1 = +bias then leaky_relu(0.01)
__global__ void __launch_bounds__(512, 1)
gemm_bf16x3(const __nv_bfloat16* __restrict__ Ah, const __nv_bfloat16* __restrict__ Al,
            const __nv_bfloat16* __restrict__ Bh, const __nv_bfloat16* __restrict__ Bl,
            float* __restrict__ C, int K, const float* __restrict__ bias)
{
    extern __shared__ char dsm[];
    uint32_t sb = (smem_u32(dsm) + 1023) & ~1023u;

    const int tid  = threadIdx.x;
    const int wid  = tid >> 5;
    const int lane = tid & 31;
    const int wm   = wid & 3;          // 4 warps along M (32 rows each)
    const int wn   = wid >> 2;         // 4 warps along N (64 cols each)
    const long bm  = (long)blockIdx.y * BM2;
    const long bn  = (long)blockIdx.x * BN2;

    const __nv_bfloat16* Aseg[3] = {Ah, Ah, Al};
    const __nv_bfloat16* Bseg[3] = {Bh, Bl, Bh};
    const int cps = K >> 6;            // K-chunks per segment
    const int nch = 3 * cps;

    float c[2][8][4];
#pragma unroll
    for (int i = 0; i < 2; i++)
#pragma unroll
        for (int j = 0; j < 8; j++)
#pragma unroll
            for (int q = 0; q < 4; q++) c[i][j][q] = 0.0f;

    // ldmatrix lane-address components (constant per thread)
    const int amat = lane >> 3;                         // 0..3
    const int arow0 = wm * 32 + (amat & 1) * 8 + (lane & 7);
    const int ahalf = amat >> 1;                        // k-half of this lane's matrix
    const int bg    = lane >> 3;
    const int bhalf = bg & 1;
    const int bn0   = wn * 64 + ((bg >> 1) << 3) + (lane & 7);

    auto loads = [&](int ch, int s) {
        int seg = (ch >= 2 * cps) ? 2 : ((ch >= cps) ? 1 : 0);
        int kk  = (ch - seg * cps) << 6;
        const __nv_bfloat16* Ab = Aseg[seg] + bm * K + kk;
        const __nv_bfloat16* Bb = Bseg[seg] + bn * K + kk;
        uint32_t As = sb + s * SMSTAGE;
        uint32_t Bs = As + SMA;
#pragma unroll
        for (int i = 0; i < 2; i++) {                  // A: 128 rows x 8 chunks
            int lin = tid * 2 + i;
            int r = lin >> 3, cc = lin & 7;
            cp_async16(As + r * 128 + ((cc ^ (r & 7)) << 4), Ab + (long)r * K + cc * 8);
        }
#pragma unroll
        for (int i = 0; i < 4; i++) {                  // B: 256 rows x 8 chunks
            int lin = tid * 4 + i;
            int r = lin >> 3, cc = lin & 7;
            cp_async16(Bs + r * 128 + ((cc ^ (r & 7)) << 4), Bb + (long)r * K + cc * 8);
        }
    };

    loads(0, 0); cp_commit();
    loads(1, 1); cp_commit();

    for (int k = 0; k < nch; k++) {
        cp_wait<1>();
        __syncthreads();               // stage k visible; prior compute done
        if (k + 2 < nch) loads(k + 2, (k + 2) % NSTAGE);
        cp_commit();

        uint32_t As = sb + (k % NSTAGE) * SMSTAGE;
        uint32_t Bs = As + SMA;
#pragma unroll
        for (int t = 0; t < 4; t++) {                  // four k16 steps
            uint32_t a[2][4];
#pragma unroll
            for (int mi = 0; mi < 2; mi++) {
                int row = arow0 + mi * 16;
                uint32_t addr = As + row * 128 + ((((2 * t) + ahalf) ^ (row & 7)) << 4);
                ldsm_x4(a[mi][0], a[mi][1], a[mi][2], a[mi][3], addr);
            }
            uint32_t b[8][2];
#pragma unroll
            for (int j = 0; j < 4; j++) {
                int n = bn0 + j * 16;
                uint32_t addr = Bs + n * 128 + ((((2 * t) + bhalf) ^ (n & 7)) << 4);
                ldsm_x4(b[2 * j][0], b[2 * j][1], b[2 * j + 1][0], b[2 * j + 1][1], addr);
            }
#pragma unroll
            for (int mi = 0; mi < 2; mi++)
#pragma unroll
                for (int nj = 0; nj < 8; nj++)
                    mma16816(c[mi][nj], a[mi], b[nj]);
        }
    }

    // Epilogue: fp32 stores (optionally bias + leaky_relu)
#pragma unroll
    for (int mi = 0; mi < 2; mi++) {
        long row = bm + wm * 32 + mi * 16 + (lane >> 2);
#pragma unroll
        for (int nj = 0; nj < 8; nj++) {
            int col = (int)bn + wn * 64 + nj * 8 + 2 * (lane & 3);
            float2 v0 = {c[mi][nj][0], c[mi][nj][1]};
            float2 v1 = {c[mi][nj][2], c[mi][nj][3]};
            if (EPI == 1) {
                float b0 = bias[col], b1 = bias[col + 1];
                v0.x += b0; v0.y += b1; v1.x += b0; v1.y += b1;
                v0.x = (v0.x >= 0.f) ? v0.x : 0.01f * v0.x;
                v0.y = (v0.y >= 0.f) ? v0.y : 0.01f * v0.y;
                v1.x = (v1.x >= 0.f) ? v1.x : 0.01f * v1.x;
                v1.y = (v1.y >= 0.f) ? v1.y : 0.01f * v1.y;
            }
            *(float2*)(C + row * DFEAT + col)       = v0;
            *(float2*)(C + (row + 8) * DFEAT + col) = v1;
        }
    }
}

// ---------------------------------------------------------------------------
// bf16 hi/lo split helpers
// ---------------------------------------------------------------------------
__device__ __forceinline__ void split1(float x, __nv_bfloat16& h, __nv_bfloat16& l) {
    h = __float2bfloat16_rn(x);
    l = __float2bfloat16_rn(x - __bfloat162float(h));
}
__device__ __forceinline__ void split_store4(__nv_bfloat16* ph, __nv_bfloat16* pl, float4 v) {
    __nv_bfloat16 h0, l0, h1, l1, h2, l2, h3, l3;
    split1(v.x, h0, l0); split1(v.y, h1, l1);
    split1(v.z, h2, l2); split1(v.w, h3, l3);
    __nv_bfloat162 hh0, hh1, ll0, ll1;
    hh0.x = h0; hh0.y = h1; hh1.x = h2; hh1.y = h3;
    ll0.x = l0; ll0.y = l1; ll1.x = l2; ll1.y = l3;
    ((__nv_bfloat162*)ph)[0] = hh0; ((__nv_bfloat162*)ph)[1] = hh1;
    ((__nv_bfloat162*)pl)[0] = ll0; ((__nv_bfloat162*)pl)[1] = ll1;
}

// features [M,512] fp32 -> hi/lo bf16, pitch 512
__global__ void split_feat_kernel(const float* __restrict__ f,
                                  __nv_bfloat16* __restrict__ ah,
                                  __nv_bfloat16* __restrict__ al)
{
    long idx = (long)blockIdx.x * blockDim.x + threadIdx.x;   // float4 units
    long total = (long)MROWS * 128;
    if (idx >= total) return;
    float4 v = ((const float4*)f)[idx];
    split_store4(ah + idx * 4, al + idx * 4, v);
}

// W [K,512] fp32 -> Wh/Wl [512,K] bf16 (transpose + split)
__global__ void split_wT_kernel(const float* __restrict__ W,
                                __nv_bfloat16* __restrict__ wh,
                                __nv_bfloat16* __restrict__ wl, int Kd)
{
    long idx = (long)blockIdx.x * blockDim.x + threadIdx.x;
    long total = (long)Kd * 512;
    if (idx >= total) return;
    int n = (int)(idx / Kd);
    int k = (int)(idx - (long)n * Kd);
    float x = __ldg(&W[(long)k * 512 + n]);
    __nv_bfloat16 h, l;
    split1(x, h, l);
    wh[idx] = h; wl[idx] = l;
}

// init rows to bias vector
__global__ void init_bias_kernel(float* __restrict__ out, const float* __restrict__ bias)
{
    long idx = (long)blockIdx.x * blockDim.x + threadIdx.x;
    long total = (long)MROWS * (DFEAT / 4);
    if (idx >= total) return;
    int j4 = (int)(idx & (DFEAT / 4 - 1));
    ((float4*)out)[idx] = ((const float4*)bias)[j4];
}

// edge scatter: dst[row[e], :] += w[e] * src[col[e], :]
__global__ void scatter_kernel(const float* __restrict__ src,
                               const int* __restrict__ rows,
                               const int* __restrict__ cols,
                               const float* __restrict__ vals,
                               float* __restrict__ dst, int nE)
{
    int e = blockIdx.x * 8 + (threadIdx.x >> 5);
    if (e >= nE) return;
    int lane = threadIdx.x & 31;
    int r = rows[e];
    int c = cols[e];
    float w = vals[e];
    const float4* s = (const float4*)(src + (long)c * DFEAT);
    float* d = dst + (long)r * DFEAT;
#pragma unroll
    for (int j = lane; j < DFEAT / 4; j += 32) {
        float4 v = s[j];
        atomicAdd(d + 4 * j + 0, w * v.x);
        atomicAdd(d + 4 * j + 1, w * v.y);
        atomicAdd(d + 4 * j + 2, w * v.z);
        atomicAdd(d + 4 * j + 3, w * v.w);
    }
}

// z = [relu(h1) | relu(feat[root])] -> bf16 hi/lo, pitch 1024
__global__ void build_z_split_kernel(const float* __restrict__ h1,
                                     const float* __restrict__ feat,
                                     const int* __restrict__ root_idx,
                                     __nv_bfloat16* __restrict__ zh,
                                     __nv_bfloat16* __restrict__ zl, int nper)
{
    long idx = (long)blockIdx.x * blockDim.x + threadIdx.x;
    long total = (long)MROWS * 128;
    if (idx >= total) return;
    long r = idx >> 7;
    int j4 = (int)(idx & 127);
    int root = root_idx[(int)(r / nper)];

    float4 h = ((const float4*)h1)[r * 128 + j4];
    float4 f = ((const float4*)feat)[(long)root * 128 + j4];
    h.x = fmaxf(h.x, 0.f); h.y = fmaxf(h.y, 0.f);
    h.z = fmaxf(h.z, 0.f); h.w = fmaxf(h.w, 0.f);
    f.x = fmaxf(f.x, 0.f); f.y = fmaxf(f.y, 0.f);
    f.z = fmaxf(f.z, 0.f); f.w = fmaxf(f.w, 0.f);

    long base = r * 1024 + j4 * 4;
    split_store4(zh + base, zl + base, h);
    split_store4(zh + base + 512, zl + base + 512, f);
}

// c2 = [relu(h2) | h1[root]] -> bf16 hi/lo, pitch 1024
__global__ void build_c2_split_kernel(const float* __restrict__ h2,
                                      const float* __restrict__ h1,
                                      const int* __restrict__ root_idx,
                                      __nv_bfloat16* __restrict__ ch,
                                      __nv_bfloat16* __restrict__ cl, int nper)
{
    long idx = (long)blockIdx.x * blockDim.x + threadIdx.x;
    long total = (long)MROWS * 128;
    if (idx >= total) return;
    long r = idx >> 7;
    int j4 = (int)(idx & 127);
    int root = root_idx[(int)(r / nper)];

    float4 h = ((const float4*)h2)[r * 128 + j4];
    float4 g = ((const float4*)h1)[(long)root * 128 + j4];
    h.x = fmaxf(h.x, 0.f); h.y = fmaxf(h.y, 0.f);
    h.z = fmaxf(h.z, 0.f); h.w = fmaxf(h.w, 0.f);

    long base = r * 1024 + j4 * 4;
    split_store4(ch + base, cl + base, h);
    split_store4(ch + base + 512, cl + base + 512, g);   // h1[root], pre-relu
}

// ---------------------------------------------------------------------------
// launch
// ---------------------------------------------------------------------------
extern "C" void kernel_launch(void* const* d_in, const int* in_sizes, int n_in,
                              void* d_out, int out_size)
{
    const float* features = (const float*)d_in[0];
    const int*   adjs     = (const int*)  d_in[1];
    const float* values   = (const float*)d_in[2];
    const int*   root_idx = (const int*)  d_in[3];
    const float* W1 = (const float*)d_in[6];
    const float* b1 = (const float*)d_in[7];
    const float* W2 = (const float*)d_in[8];
    const float* b2 = (const float*)d_in[9];
    const float* Wl = (const float*)d_in[10];
    const float* bl = (const float*)d_in[11];
    float* out = (float*)d_out;

    const int nE   = in_sizes[2];
    const int Bg   = in_sizes[3];
    const int nper = (in_sizes[0] / DFEAT) / Bg;

    float *support, *h1, *h2;
    __nv_bfloat16 *ah, *al, *w1h, *w1l, *w2h, *w2l, *wlh, *wll;
    cudaGetSymbolAddress((void**)&support, g_support);
    cudaGetSymbolAddress((void**)&h1,      g_h1);
    cudaGetSymbolAddress((void**)&h2,      g_h2);
    cudaGetSymbolAddress((void**)&ah,      g_ah);
    cudaGetSymbolAddress((void**)&al,      g_al);
    cudaGetSymbolAddress((void**)&w1h,     g_w1h);
    cudaGetSymbolAddress((void**)&w1l,     g_w1l);
    cudaGetSymbolAddress((void**)&w2h,     g_w2h);
    cudaGetSymbolAddress((void**)&w2l,     g_w2l);
    cudaGetSymbolAddress((void**)&wlh,     g_wlh);
    cudaGetSymbolAddress((void**)&wll,     g_wll);

    const int* rows = adjs;
    const int* cols = adjs + nE;

    cudaFuncSetAttribute(gemm_bf16x3<0>, cudaFuncAttributeMaxDynamicSharedMemorySize, SMTOTAL);
    cudaFuncSetAttribute(gemm_bf16x3<1>, cudaFuncAttributeMaxDynamicSharedMemorySize, SMTOTAL);

    dim3 ggrid(DFEAT / BN2, MROWS / BM2);            // (2, 512)
    const long ew_total = (long)MROWS * 128;
    const int  ew_blocks = (int)((ew_total + 255) / 256);
    const int  sc_blocks = (nE + 7) / 8;

    // 0) weight splits (transposed to [N,K]) + feature split
    split_wT_kernel<<<(512 * 512 + 255) / 256, 256>>>(W1, w1h, w1l, 512);
    split_wT_kernel<<<(512 * 1024 + 255) / 256, 256>>>(W2, w2h, w2l, 1024);
    split_wT_kernel<<<(512 * 1024 + 255) / 256, 256>>>(Wl, wlh, wll, 1024);
    split_feat_kernel<<<ew_blocks, 256>>>(features, ah, al);

    // 1) support1 = X @ W1
    gemm_bf16x3<0><<<ggrid, 512, SMTOTAL>>>(ah, al, w1h, w1l, support, 512, nullptr);
    // 2) h1 = b1; h1[row] += w * support1[col]
    init_bias_kernel<<<ew_blocks, 256>>>(h1, b1);
    scatter_kernel<<<sc_blocks, 256>>>(support, rows, cols, values, h1, nE);
    // 3) z = [relu(h1) | relu(x[root])] (split to bf16)
    build_z_split_kernel<<<ew_blocks, 256>>>(h1, features, root_idx, ah, al, nper);
    // 4) support2 = z @ W2
    gemm_bf16x3<0><<<ggrid, 512, SMTOTAL>>>(ah, al, w2h, w2l, support, 1024, nullptr);
    // 5) h2 = b2; h2[row] += w * support2[col]
    init_bias_kernel<<<ew_blocks, 256>>>(h2, b2);
    scatter_kernel<<<sc_blocks, 256>>>(support, rows, cols, values, h2, nE);
    // 6) c2 = [relu(h2) | h1[root]] (split to bf16)
    build_c2_split_kernel<<<ew_blocks, 256>>>(h2, h1, root_idx, ah, al, nper);
    // 7) out = leaky_relu(c2 @ Wl + bl)
    gemm_bf16x3<1><<<ggrid, 512, SMTOTAL>>>(ah, al, wlh, wll, out, 1024, bl);
}

// round 4
// speedup vs baseline: 2.8251x; 1.3593x over previous
#include <cuda_runtime.h>
#include <cuda_bf16.h>
#include <cstdint>

#define MROWS   65536
#define DFEAT   512
#define NEDGES  65536
#define NGRAPH  16
#define GSHIFT  12          // rows per graph = 4096 = 1<<12

// ---------------------------------------------------------------------------
// Scratch (__device__ globals; allocation-free)
// ---------------------------------------------------------------------------
__device__ float g_support[(size_t)MROWS * DFEAT];
__device__ float g_h1[(size_t)MROWS * DFEAT];
__device__ float g_h2[(size_t)MROWS * DFEAT];
__device__ float g_S[MROWS];                          // per-row edge-weight sums
__device__ float g_rt[NGRAPH * DFEAT];                // relu(x[root]) @ W2b
__device__ float g_rt2[NGRAPH * DFEAT];               // bl + h1[root] @ Wlb
__device__ __nv_bfloat16 g_ah[(size_t)MROWS * DFEAT]; // A-hi
__device__ __nv_bfloat16 g_al[(size_t)MROWS * DFEAT]; // A-lo
__device__ __nv_bfloat16 g_w1h[512 * 512], g_w1l[512 * 512];
__device__ __nv_bfloat16 g_w2h[512 * 512], g_w2l[512 * 512];   // W2a^T
__device__ __nv_bfloat16 g_wlh[512 * 512], g_wll[512 * 512];   // Wla^T

// ---------------------------------------------------------------------------
// PTX helpers (cp.async / ldmatrix / mma.sync — plain sm_80+ PTX)
// ---------------------------------------------------------------------------
__device__ __forceinline__ uint32_t smem_u32(const void* p) {
    return (uint32_t)__cvta_generic_to_shared(p);
}
__device__ __forceinline__ void cp_async16(uint32_t dst, const void* src) {
    asm volatile("cp.async.cg.shared.global [%0], [%1], 16;" :: "r"(dst), "l"(src));
}
__device__ __forceinline__ void cp_commit() {
    asm volatile("cp.async.commit_group;");
}
template<int N>
__device__ __forceinline__ void cp_wait() {
    asm volatile("cp.async.wait_group %0;" :: "n"(N));
}
__device__ __forceinline__ void ldsm_x4(uint32_t& r0, uint32_t& r1,
                                        uint32_t& r2, uint32_t& r3, uint32_t a) {
    asm volatile("ldmatrix.sync.aligned.m8n8.x4.shared.b16 {%0,%1,%2,%3}, [%4];"
                 : "=r"(r0), "=r"(r1), "=r"(r2), "=r"(r3) : "r"(a));
}
__device__ __forceinline__ void mma16816(float* c, const uint32_t* a, const uint32_t* b) {
    asm volatile(
        "mma.sync.aligned.m16n8k16.row.col.f32.bf16.bf16.f32 "
        "{%0,%1,%2,%3}, {%4,%5,%6,%7}, {%8,%9}, {%0,%1,%2,%3};"
        : "+f"(c[0]), "+f"(c[1]), "+f"(c[2]), "+f"(c[3])
        : "r"(a[0]), "r"(a[1]), "r"(a[2]), "r"(a[3]), "r"(b[0]), "r"(b[1]));
}

// ---------------------------------------------------------------------------
// bf16x3 split GEMM on tensor cores: C[M,512] = (Ah+Al)[M,512] @ (Bh+Bl)[512,512]^T
// CTA tile 128x256, 512 threads, BK=64, 3-stage cp.async, swizzled smem.
// EPI: 0 = plain store; 2 = + per-graph bias row then leaky_relu(0.01)
// ---------------------------------------------------------------------------
#define BM2 128
#define BN2 256
#define NSTAGE 3
#define SMA (BM2 * 128)
#define SMB (BN2 * 128)
#define SMSTAGE (SMA + SMB)
#define SMTOTAL (NSTAGE * SMSTAGE + 1024)

template<int EPI>
__global__ void __launch_bounds__(512, 1)
gemm_bf16x3(const __nv_bfloat16* __restrict__ Ah, const __nv_bfloat16* __restrict__ Al,
            const __nv_bfloat16* __restrict__ Bh, const __nv_bfloat16* __restrict__ Bl,
            float* __restrict__ C, const float* __restrict__ bias)
{
    constexpr int K = 512;
    extern __shared__ char dsm[];
    uint32_t sb = (smem_u32(dsm) + 1023) & ~1023u;

    const int tid  = threadIdx.x;
    const int lane = tid & 31;
    const int wid  = tid >> 5;
    const int wm   = wid & 3;
    const int wn   = wid >> 2;
    const long bm  = (long)blockIdx.y * BM2;
    const long bn  = (long)blockIdx.x * BN2;

    const __nv_bfloat16* Aseg[3] = {Ah, Ah, Al};
    const __nv_bfloat16* Bseg[3] = {Bh, Bl, Bh};
    const int cps = K >> 6;           // 8
    const int nch = 3 * cps;          // 24

    float c[2][8][4];
#pragma unroll
    for (int i = 0; i < 2; i++)
#pragma unroll
        for (int j = 0; j < 8; j++)
#pragma unroll
            for (int q = 0; q < 4; q++) c[i][j][q] = 0.0f;

    const int amat  = lane >> 3;
    const int arow0 = wm * 32 + (amat & 1) * 8 + (lane & 7);
    const int ahalf = amat >> 1;
    const int bg    = lane >> 3;
    const int bhalf = bg & 1;
    const int bn0   = wn * 64 + ((bg >> 1) << 3) + (lane & 7);

    auto loads = [&](int ch, int s) {
        int seg = (ch >= 2 * cps) ? 2 : ((ch >= cps) ? 1 : 0);
        int kk  = (ch - seg * cps) << 6;
        const __nv_bfloat16* Ab = Aseg[seg] + bm * K + kk;
        const __nv_bfloat16* Bb = Bseg[seg] + bn * K + kk;
        uint32_t As = sb + s * SMSTAGE;
        uint32_t Bs = As + SMA;
#pragma unroll
        for (int i = 0; i < 2; i++) {
            int lin = tid * 2 + i;
            int r = lin >> 3, cc = lin & 7;
            cp_async16(As + r * 128 + ((cc ^ (r & 7)) << 4), Ab + (long)r * K + cc * 8);
        }
#pragma unroll
        for (int i = 0; i < 4; i++) {
            int lin = tid * 4 + i;
            int r = lin >> 3, cc = lin & 7;
            cp_async16(Bs + r * 128 + ((cc ^ (r & 7)) << 4), Bb + (long)r * K + cc * 8);
        }
    };

    loads(0, 0); cp_commit();
    loads(1, 1); cp_commit();

    for (int k = 0; k < nch; k++) {
        cp_wait<1>();
        __syncthreads();
        if (k + 2 < nch) loads(k + 2, (k + 2) % NSTAGE);
        cp_commit();

        uint32_t As = sb + (k % NSTAGE) * SMSTAGE;
        uint32_t Bs = As + SMA;
#pragma unroll
        for (int t = 0; t < 4; t++) {
            uint32_t a[2][4];
#pragma unroll
            for (int mi = 0; mi < 2; mi++) {
                int row = arow0 + mi * 16;
                uint32_t addr = As + row * 128 + ((((2 * t) + ahalf) ^ (row & 7)) << 4);
                ldsm_x4(a[mi][0], a[mi][1], a[mi][2], a[mi][3], addr);
            }
            uint32_t b[8][2];
#pragma unroll
            for (int j = 0; j < 4; j++) {
                int n = bn0 + j * 16;
                uint32_t addr = Bs + n * 128 + ((((2 * t) + bhalf) ^ (n & 7)) << 4);
                ldsm_x4(b[2 * j][0], b[2 * j][1], b[2 * j + 1][0], b[2 * j + 1][1], addr);
            }
#pragma unroll
            for (int mi = 0; mi < 2; mi++)
#pragma unroll
                for (int nj = 0; nj < 8; nj++)
                    mma16816(c[mi][nj], a[mi], b[nj]);
        }
    }

#pragma unroll
    for (int mi = 0; mi < 2; mi++) {
        long row = bm + wm * 32 + mi * 16 + (lane >> 2);
        const float* bp = (EPI == 2) ? bias + ((row >> GSHIFT) << 9) : nullptr;
#pragma unroll
        for (int nj = 0; nj < 8; nj++) {
            int col = (int)bn + wn * 64 + nj * 8 + 2 * (lane & 3);
            float2 v0 = {c[mi][nj][0], c[mi][nj][1]};
            float2 v1 = {c[mi][nj][2], c[mi][nj][3]};
            if (EPI == 2) {
                float b0 = bp[col], b1 = bp[col + 1];
                v0.x += b0; v0.y += b1; v1.x += b0; v1.y += b1;
                v0.x = (v0.x >= 0.f) ? v0.x : 0.01f * v0.x;
                v0.y = (v0.y >= 0.f) ? v0.y : 0.01f * v0.y;
                v1.x = (v1.x >= 0.f) ? v1.x : 0.01f * v1.x;
                v1.y = (v1.y >= 0.f) ? v1.y : 0.01f * v1.y;
            }
            *(float2*)(C + row * DFEAT + col)       = v0;
            *(float2*)(C + (row + 8) * DFEAT + col) = v1;
        }
    }
}

// ---------------------------------------------------------------------------
// split helpers & elementwise kernels
// ---------------------------------------------------------------------------
__device__ __forceinline__ void split1(float x, __nv_bfloat16& h, __nv_bfloat16& l) {
    h = __float2bfloat16_rn(x);
    l = __float2bfloat16_rn(x - __bfloat162float(h));
}
__device__ __forceinline__ void split_store4(__nv_bfloat16* ph, __nv_bfloat16* pl, float4 v) {
    __nv_bfloat16 h0, l0, h1, l1, h2, l2, h3, l3;
    split1(v.x, h0, l0); split1(v.y, h1, l1);
    split1(v.z, h2, l2); split1(v.w, h3, l3);
    __nv_bfloat162 hh0, hh1, ll0, ll1;
    hh0.x = h0; hh0.y = h1; hh1.x = h2; hh1.y = h3;
    ll0.x = l0; ll0.y = l1; ll1.x = l2; ll1.y = l3;
    ((__nv_bfloat162*)ph)[0] = hh0; ((__nv_bfloat162*)ph)[1] = hh1;
    ((__nv_bfloat162*)pl)[0] = ll0; ((__nv_bfloat162*)pl)[1] = ll1;
}

// src [M,512] fp32 -> hi/lo bf16 (optional relu), pitch 512
template<int RELU>
__global__ void split_kernel(const float* __restrict__ f,
                             __nv_bfloat16* __restrict__ ah,
                             __nv_bfloat16* __restrict__ al)
{
    long idx = (long)blockIdx.x * blockDim.x + threadIdx.x;
    long total = (long)MROWS * 128;
    if (idx >= total) return;
    float4 v = ((const float4*)f)[idx];
    if (RELU) {
        v.x = fmaxf(v.x, 0.f); v.y = fmaxf(v.y, 0.f);
        v.z = fmaxf(v.z, 0.f); v.w = fmaxf(v.w, 0.f);
    }
    split_store4(ah + idx * 4, al + idx * 4, v);
}

// W [512,512] fp32 (rows k, cols n) -> Wh/Wl [512,512] bf16 transposed [n,k]
__global__ void split_wT_kernel(const float* __restrict__ W,
                                __nv_bfloat16* __restrict__ wh,
                                __nv_bfloat16* __restrict__ wl)
{
    long idx = (long)blockIdx.x * blockDim.x + threadIdx.x;
    if (idx >= 512 * 512) return;
    int n = (int)(idx >> 9);
    int k = (int)(idx & 511);
    float x = __ldg(&W[(long)k * 512 + n]);
    __nv_bfloat16 h, l;
    split1(x, h, l);
    wh[idx] = h; wl[idx] = l;
}

// out[i,:] = bias
__global__ void init_bias_kernel(float* __restrict__ out, const float* __restrict__ bias)
{
    long idx = (long)blockIdx.x * blockDim.x + threadIdx.x;
    if (idx >= (long)MROWS * 128) return;
    int j4 = (int)(idx & 127);
    ((float4*)out)[idx] = ((const float4*)bias)[j4];
}

// h2[r,:] = b2 + S[r] * rt[g(r),:]
__global__ void init_h2_kernel(float* __restrict__ out, const float* __restrict__ b2,
                               const float* __restrict__ S, const float* __restrict__ rt)
{
    long idx = (long)blockIdx.x * blockDim.x + threadIdx.x;
    if (idx >= (long)MROWS * 128) return;
    long r = idx >> 7;
    int j4 = (int)(idx & 127);
    float s = S[r];
    float4 bb = ((const float4*)b2)[j4];
    float4 rr = ((const float4*)rt)[((r >> GSHIFT) << 7) + j4];
    bb.x += s * rr.x; bb.y += s * rr.y; bb.z += s * rr.z; bb.w += s * rr.w;
    ((float4*)out)[idx] = bb;
}

// S: zero then accumulate edge weights per destination row
__global__ void zero_S_kernel(float* __restrict__ S)
{
    int i = blockIdx.x * blockDim.x + threadIdx.x;
    if (i < MROWS) S[i] = 0.0f;
}
__global__ void accum_S_kernel(const int* __restrict__ rows,
                               const float* __restrict__ vals,
                               float* __restrict__ S, int nE)
{
    int e = blockIdx.x * blockDim.x + threadIdx.x;
    if (e < nE) atomicAdd(S + rows[e], vals[e]);
}

// edge scatter: dst[row[e], :] += w[e] * src[col[e], :]
__global__ void scatter_kernel(const float* __restrict__ src,
                               const int* __restrict__ rows,
                               const int* __restrict__ cols,
                               const float* __restrict__ vals,
                               float* __restrict__ dst, int nE)
{
    int e = blockIdx.x * 8 + (threadIdx.x >> 5);
    if (e >= nE) return;
    int lane = threadIdx.x & 31;
    int r = rows[e];
    int c = cols[e];
    float w = vals[e];
    const float4* s = (const float4*)(src + (long)c * DFEAT);
    float* d = dst + (long)r * DFEAT;
#pragma unroll
    for (int j = lane; j < DFEAT / 4; j += 32) {
        float4 v = s[j];
        atomicAdd(d + 4 * j + 0, w * v.x);
        atomicAdd(d + 4 * j + 1, w * v.y);
        atomicAdd(d + 4 * j + 2, w * v.z);
        atomicAdd(d + 4 * j + 3, w * v.w);
    }
}

// rt[g,n] = sum_k act(vecsrc[root_g, k]) * Wfull[(512+k)*512 + n]  (+ optional bias)
// RELU=1: relu the gathered root vector (for z's rx half). bias may be null.
template<int RELU>
__global__ void root_term_kernel(const float* __restrict__ vecsrc,
                                 const int* __restrict__ root_idx,
                                 const float* __restrict__ Wfull,
                                 const float* __restrict__ bias,
                                 float* __restrict__ rt)
{
    int g = blockIdx.y;
    int n = blockIdx.x * blockDim.x + threadIdx.x;    // 0..511
    const float* v = vecsrc + (long)root_idx[g] * DFEAT;
    float acc = (bias != nullptr) ? bias[n] : 0.0f;
    const float* Wb = Wfull + (long)512 * 512 + n;    // rows 512..1023
#pragma unroll 4
    for (int k = 0; k < 512; k++) {
        float x = __ldg(v + k);
        if (RELU) x = fmaxf(x, 0.f);
        acc += x * __ldg(Wb + (long)k * 512);
    }
    rt[g * DFEAT + n] = acc;
}

// ---------------------------------------------------------------------------
// launch
// ---------------------------------------------------------------------------
extern "C" void kernel_launch(void* const* d_in, const int* in_sizes, int n_in,
                              void* d_out, int out_size)
{
    const float* features = (const float*)d_in[0];
    const int*   adjs     = (const int*)  d_in[1];
    const float* values   = (const float*)d_in[2];
    const int*   root_idx = (const int*)  d_in[3];
    const float* W1 = (const float*)d_in[6];
    const float* b1 = (const float*)d_in[7];
    const float* W2 = (const float*)d_in[8];
    const float* b2 = (const float*)d_in[9];
    const float* Wl = (const float*)d_in[10];
    const float* bl = (const float*)d_in[11];
    float* out = (float*)d_out;

    const int nE = in_sizes[2];

    float *support, *h1, *h2, *S, *rt, *rt2;
    __nv_bfloat16 *ah, *al, *w1h, *w1l, *w2h, *w2l, *wlh, *wll;
    cudaGetSymbolAddress((void**)&support, g_support);
    cudaGetSymbolAddress((void**)&h1,  g_h1);
    cudaGetSymbolAddress((void**)&h2,  g_h2);
    cudaGetSymbolAddress((void**)&S,   g_S);
    cudaGetSymbolAddress((void**)&rt,  g_rt);
    cudaGetSymbolAddress((void**)&rt2, g_rt2);
    cudaGetSymbolAddress((void**)&ah,  g_ah);
    cudaGetSymbolAddress((void**)&al,  g_al);
    cudaGetSymbolAddress((void**)&w1h, g_w1h);
    cudaGetSymbolAddress((void**)&w1l, g_w1l);
    cudaGetSymbolAddress((void**)&w2h, g_w2h);
    cudaGetSymbolAddress((void**)&w2l, g_w2l);
    cudaGetSymbolAddress((void**)&wlh, g_wlh);
    cudaGetSymbolAddress((void**)&wll, g_wll);

    const int* rows = adjs;
    const int* cols = adjs + nE;

    cudaFuncSetAttribute(gemm_bf16x3<0>, cudaFuncAttributeMaxDynamicSharedMemorySize, SMTOTAL);
    cudaFuncSetAttribute(gemm_bf16x3<2>, cudaFuncAttributeMaxDynamicSharedMemorySize, SMTOTAL);

    dim3 ggrid(DFEAT / BN2, MROWS / BM2);             // (2, 512)
    const int ew_blocks = (int)(((long)MROWS * 128 + 255) / 256);
    const int sc_blocks = (nE + 7) / 8;
    dim3 rt_grid(2, NGRAPH);

    // 0) weight splits (first 512 rows, transposed) + feature split + S
    split_wT_kernel<<<(512 * 512 + 255) / 256, 256>>>(W1, w1h, w1l);
    split_wT_kernel<<<(512 * 512 + 255) / 256, 256>>>(W2, w2h, w2l);
    split_wT_kernel<<<(512 * 512 + 255) / 256, 256>>>(Wl, wlh, wll);
    split_kernel<0><<<ew_blocks, 256>>>(features, ah, al);
    zero_S_kernel<<<(MROWS + 255) / 256, 256>>>(S);
    accum_S_kernel<<<(nE + 255) / 256, 256>>>(rows, values, S, nE);
    // root term for conv2: rt[g] = relu(x[root_g]) @ W2[512:,:]
    root_term_kernel<1><<<rt_grid, 256>>>(features, root_idx, W2, nullptr, rt);

    // 1) support = X @ W1
    gemm_bf16x3<0><<<ggrid, 512, SMTOTAL>>>(ah, al, w1h, w1l, support, nullptr);
    // 2) h1 = b1 + scatter
    init_bias_kernel<<<ew_blocks, 256>>>(h1, b1);
    scatter_kernel<<<sc_blocks, 256>>>(support, rows, cols, values, h1, nE);
    // 3) split relu(h1); rt2[g] = bl + h1[root_g] @ Wl[512:,:]
    split_kernel<1><<<ew_blocks, 256>>>(h1, ah, al);
    root_term_kernel<0><<<rt_grid, 256>>>(h1, root_idx, Wl, bl, rt2);
    // 4) support = relu(h1) @ W2a
    gemm_bf16x3<0><<<ggrid, 512, SMTOTAL>>>(ah, al, w2h, w2l, support, nullptr);
    // 5) h2 = b2 + S*rt[g] + scatter
    init_h2_kernel<<<ew_blocks, 256>>>(h2, b2, S, rt);
    scatter_kernel<<<sc_blocks, 256>>>(support, rows, cols, values, h2, nE);
    // 6) split relu(h2)
    split_kernel<1><<<ew_blocks, 256>>>(h2, ah, al);
    // 7) out = leaky_relu(relu(h2) @ Wla + rt2[g])
    gemm_bf16x3<2><<<ggrid, 512, SMTOTAL>>>(ah, al, wlh, wll, out, rt2);
}

// round 5
// speedup vs baseline: 2.8858x; 1.0215x over previous
#include <cuda_runtime.h>
#include <cuda_bf16.h>
#include <cstdint>

#define MROWS   65536
#define DFEAT   512
#define NEDGES  65536
#define NGRAPH  16
#define GSHIFT  12          // rows per graph = 4096

// ---------------------------------------------------------------------------
// Scratch (__device__ globals; allocation-free)
// ---------------------------------------------------------------------------
__device__ float g_S[MROWS];                       // per-row edge-weight sums
__device__ float g_rt[NGRAPH * DFEAT];             // relu(x[root]) @ W2b
__device__ float g_rt2[NGRAPH * DFEAT];            // bl + h1[root] @ Wlb
__device__ float g_h1root[NGRAPH * DFEAT];         // pre-relu h1 at root rows
__device__ __nv_bfloat16 g_ah[(size_t)MROWS * DFEAT], g_al[(size_t)MROWS * DFEAT];
__device__ __nv_bfloat16 g_bh[(size_t)MROWS * DFEAT], g_bl[(size_t)MROWS * DFEAT];
__device__ __nv_bfloat16 g_w1h[512 * 512], g_w1l[512 * 512];
__device__ __nv_bfloat16 g_w2h[512 * 512], g_w2l[512 * 512];   // W2a^T
__device__ __nv_bfloat16 g_wlh[512 * 512], g_wll[512 * 512];   // Wla^T
// CSR
__device__ int   g_cnt[MROWS];
__device__ int   g_offs[MROWS + 1];
__device__ int   g_cursor[MROWS];
__device__ int   g_ecol[NEDGES];
__device__ float g_ew[NEDGES];

// ---------------------------------------------------------------------------
// PTX helpers
// ---------------------------------------------------------------------------
__device__ __forceinline__ uint32_t smem_u32(const void* p) {
    return (uint32_t)__cvta_generic_to_shared(p);
}
__device__ __forceinline__ void cp_async16(uint32_t dst, const void* src) {
    asm volatile("cp.async.cg.shared.global [%0], [%1], 16;" :: "r"(dst), "l"(src));
}
__device__ __forceinline__ void cp_commit() {
    asm volatile("cp.async.commit_group;");
}
template<int N>
__device__ __forceinline__ void cp_wait() {
    asm volatile("cp.async.wait_group %0;" :: "n"(N));
}
__device__ __forceinline__ void ldsm_x4(uint32_t& r0, uint32_t& r1,
                                        uint32_t& r2, uint32_t& r3, uint32_t a) {
    asm volatile("ldmatrix.sync.aligned.m8n8.x4.shared.b16 {%0,%1,%2,%3}, [%4];"
                 : "=r"(r0), "=r"(r1), "=r"(r2), "=r"(r3) : "r"(a));
}
__device__ __forceinline__ void mma16816(float* c, const uint32_t* a, const uint32_t* b) {
    asm volatile(
        "mma.sync.aligned.m16n8k16.row.col.f32.bf16.bf16.f32 "
        "{%0,%1,%2,%3}, {%4,%5,%6,%7}, {%8,%9}, {%0,%1,%2,%3};"
        : "+f"(c[0]), "+f"(c[1]), "+f"(c[2]), "+f"(c[3])
        : "r"(a[0]), "r"(a[1]), "r"(a[2]), "r"(a[3]), "r"(b[0]), "r"(b[1]));
}

// ---------------------------------------------------------------------------
// split helpers
// ---------------------------------------------------------------------------
__device__ __forceinline__ void split1(float x, __nv_bfloat16& h, __nv_bfloat16& l) {
    h = __float2bfloat16_rn(x);
    l = __float2bfloat16_rn(x - __bfloat162float(h));
}
__device__ __forceinline__ void split_store2(__nv_bfloat16* ph, __nv_bfloat16* pl, float2 v) {
    __nv_bfloat16 h0, l0, h1, l1;
    split1(v.x, h0, l0); split1(v.y, h1, l1);
    __nv_bfloat162 hh, ll;
    hh.x = h0; hh.y = h1; ll.x = l0; ll.y = l1;
    *(__nv_bfloat162*)ph = hh; *(__nv_bfloat162*)pl = ll;
}
__device__ __forceinline__ void split_store4(__nv_bfloat16* ph, __nv_bfloat16* pl, float4 v) {
    split_store2(ph,     pl,     make_float2(v.x, v.y));
    split_store2(ph + 2, pl + 2, make_float2(v.z, v.w));
}

// ---------------------------------------------------------------------------
// bf16x3 split GEMM: C = (Ah+Al)[M,512] @ (Bh+Bl)[512,512]^T
// EPI=3: +bias(col); store pre-relu fp32 at root rows; relu; split->Oh/Ol
// EPI=4: +bias(col)+S[row]*rt[g,col]; relu; split->Oh/Ol
// EPI=2: +rt2[g,col]; leaky_relu; fp32 store -> C
// ---------------------------------------------------------------------------
#define BM2 128
#define BN2 256
#define NSTAGE 3
#define SMA (BM2 * 128)
#define SMB (BN2 * 128)
#define SMSTAGE (SMA + SMB)
#define SMTOTAL (NSTAGE * SMSTAGE + 1024)

template<int EPI>
__global__ void __launch_bounds__(512, 1)
gemm_bf16x3(const __nv_bfloat16* __restrict__ Ah, const __nv_bfloat16* __restrict__ Al,
            const __nv_bfloat16* __restrict__ Bh, const __nv_bfloat16* __restrict__ Bl,
            float* __restrict__ C,
            __nv_bfloat16* __restrict__ Oh, __nv_bfloat16* __restrict__ Ol,
            const float* __restrict__ bias, const float* __restrict__ rt,
            const float* __restrict__ S, const int* __restrict__ root_idx,
            float* __restrict__ h1root)
{
    constexpr int K = 512;
    extern __shared__ char dsm[];
    uint32_t sb = (smem_u32(dsm) + 1023) & ~1023u;

    const int tid  = threadIdx.x;
    const int lane = tid & 31;
    const int wid  = tid >> 5;
    const int wm   = wid & 3;
    const int wn   = wid >> 2;
    const long bm  = (long)blockIdx.y * BM2;
    const long bn  = (long)blockIdx.x * BN2;

    const __nv_bfloat16* Aseg[3] = {Ah, Ah, Al};
    const __nv_bfloat16* Bseg[3] = {Bh, Bl, Bh};
    const int cps = K >> 6;
    const int nch = 3 * cps;

    float c[2][8][4];
#pragma unroll
    for (int i = 0; i < 2; i++)
#pragma unroll
        for (int j = 0; j < 8; j++)
#pragma unroll
            for (int q = 0; q < 4; q++) c[i][j][q] = 0.0f;

    const int amat  = lane >> 3;
    const int arow0 = wm * 32 + (amat & 1) * 8 + (lane & 7);
    const int ahalf = amat >> 1;
    const int bg    = lane >> 3;
    const int bhalf = bg & 1;
    const int bn0   = wn * 64 + ((bg >> 1) << 3) + (lane & 7);

    auto loads = [&](int ch, int s) {
        int seg = (ch >= 2 * cps) ? 2 : ((ch >= cps) ? 1 : 0);
        int kk  = (ch - seg * cps) << 6;
        const __nv_bfloat16* Ab = Aseg[seg] + bm * K + kk;
        const __nv_bfloat16* Bb = Bseg[seg] + bn * K + kk;
        uint32_t As = sb + s * SMSTAGE;
        uint32_t Bs = As + SMA;
#pragma unroll
        for (int i = 0; i < 2; i++) {
            int lin = tid * 2 + i;
            int r = lin >> 3, cc = lin & 7;
            cp_async16(As + r * 128 + ((cc ^ (r & 7)) << 4), Ab + (long)r * K + cc * 8);
        }
#pragma unroll
        for (int i = 0; i < 4; i++) {
            int lin = tid * 4 + i;
            int r = lin >> 3, cc = lin & 7;
            cp_async16(Bs + r * 128 + ((cc ^ (r & 7)) << 4), Bb + (long)r * K + cc * 8);
        }
    };

    loads(0, 0); cp_commit();
    loads(1, 1); cp_commit();

    for (int k = 0; k < nch; k++) {
        cp_wait<1>();
        __syncthreads();
        if (k + 2 < nch) loads(k + 2, (k + 2) % NSTAGE);
        cp_commit();

        uint32_t As = sb + (k % NSTAGE) * SMSTAGE;
        uint32_t Bs = As + SMA;
#pragma unroll
        for (int t = 0; t < 4; t++) {
            uint32_t a[2][4];
#pragma unroll
            for (int mi = 0; mi < 2; mi++) {
                int row = arow0 + mi * 16;
                uint32_t addr = As + row * 128 + ((((2 * t) + ahalf) ^ (row & 7)) << 4);
                ldsm_x4(a[mi][0], a[mi][1], a[mi][2], a[mi][3], addr);
            }
            uint32_t b[8][2];
#pragma unroll
            for (int j = 0; j < 4; j++) {
                int n = bn0 + j * 16;
                uint32_t addr = Bs + n * 128 + ((((2 * t) + bhalf) ^ (n & 7)) << 4);
                ldsm_x4(b[2 * j][0], b[2 * j][1], b[2 * j + 1][0], b[2 * j + 1][1], addr);
            }
#pragma unroll
            for (int mi = 0; mi < 2; mi++)
#pragma unroll
                for (int nj = 0; nj < 8; nj++)
                    mma16816(c[mi][nj], a[mi], b[nj]);
        }
    }

#pragma unroll
    for (int mi = 0; mi < 2; mi++) {
        long row = bm + wm * 32 + mi * 16 + (lane >> 2);
        int g = (int)(row >> GSHIFT);
#pragma unroll
        for (int nj = 0; nj < 8; nj++) {
            int col = (int)bn + wn * 64 + nj * 8 + 2 * (lane & 3);
            float2 v0 = {c[mi][nj][0], c[mi][nj][1]};   // row
            float2 v1 = {c[mi][nj][2], c[mi][nj][3]};   // row + 8

            if (EPI == 3) {
                float b0 = bias[col], b1v = bias[col + 1];
                v0.x += b0; v0.y += b1v; v1.x += b0; v1.y += b1v;
                int rr = root_idx[g];
                if ((long)rr == row) {
                    h1root[g * 512 + col] = v0.x; h1root[g * 512 + col + 1] = v0.y;
                }
                if ((long)rr == row + 8) {
                    h1root[g * 512 + col] = v1.x; h1root[g * 512 + col + 1] = v1.y;
                }
                v0.x = fmaxf(v0.x, 0.f); v0.y = fmaxf(v0.y, 0.f);
                v1.x = fmaxf(v1.x, 0.f); v1.y = fmaxf(v1.y, 0.f);
                split_store2(Oh + row * 512 + col,       Ol + row * 512 + col,       v0);
                split_store2(Oh + (row + 8) * 512 + col, Ol + (row + 8) * 512 + col, v1);
            } else if (EPI == 4) {
                float s0 = S[row], s1 = S[row + 8];
                float r0 = rt[g * 512 + col], r1 = rt[g * 512 + col + 1];
                float b0 = bias[col], b1v = bias[col + 1];
                v0.x += b0 + s0 * r0; v0.y += b1v + s0 * r1;
                v1.x += b0 + s1 * r0; v1.y += b1v + s1 * r1;
                v0.x = fmaxf(v0.x, 0.f); v0.y = fmaxf(v0.y, 0.f);
                v1.x = fmaxf(v1.x, 0.f); v1.y = fmaxf(v1.y, 0.f);
                split_store2(Oh + row * 512 + col,       Ol + row * 512 + col,       v0);
                split_store2(Oh + (row + 8) * 512 + col, Ol + (row + 8) * 512 + col, v1);
            } else {  // EPI == 2
                float b0 = rt[g * 512 + col], b1v = rt[g * 512 + col + 1];
                v0.x += b0; v0.y += b1v; v1.x += b0; v1.y += b1v;
                v0.x = (v0.x >= 0.f) ? v0.x : 0.01f * v0.x;
                v0.y = (v0.y >= 0.f) ? v0.y : 0.01f * v0.y;
                v1.x = (v1.x >= 0.f) ? v1.x : 0.01f * v1.x;
                v1.y = (v1.y >= 0.f) ? v1.y : 0.01f * v1.y;
                *(float2*)(C + row * 512 + col)       = v0;
                *(float2*)(C + (row + 8) * 512 + col) = v1;
            }
        }
    }
}

// ---------------------------------------------------------------------------
// CSR build
// ---------------------------------------------------------------------------
__global__ void zero_cnt_kernel(int* __restrict__ cnt)
{
    int i = blockIdx.x * blockDim.x + threadIdx.x;
    if (i < MROWS) cnt[i] = 0;
}
__global__ void hist_kernel(const int* __restrict__ rows, int* __restrict__ cnt, int nE)
{
    int e = blockIdx.x * blockDim.x + threadIdx.x;
    if (e < nE) atomicAdd(&cnt[rows[e]], 1);
}
// single block, 1024 threads; 64 rows per thread
__global__ void __launch_bounds__(1024, 1)
scan_kernel(const int* __restrict__ cnt, int* __restrict__ offs, int* __restrict__ cursor)
{
    __shared__ int ts[1024];
    const int tid = threadIdx.x;
    const int base = tid * 64;
    int local = 0;
#pragma unroll 8
    for (int i = 0; i < 64; i++) local += cnt[base + i];
    int x = local;
    ts[tid] = x; __syncthreads();
    for (int s = 1; s < 1024; s <<= 1) {
        int v = (tid >= s) ? ts[tid - s] : 0;
        __syncthreads();
        x += v; ts[tid] = x; __syncthreads();
    }
    int run = x - local;   // exclusive prefix of this chunk
    for (int i = 0; i < 64; i++) {
        int cc = cnt[base + i];
        offs[base + i] = run;
        cursor[base + i] = run;
        run += cc;
    }
    if (tid == 1023) offs[MROWS] = run;
}
__global__ void fill_csr_kernel(const int* __restrict__ rows, const int* __restrict__ cols,
                                const float* __restrict__ vals, int* __restrict__ cursor,
                                int* __restrict__ ecol, float* __restrict__ ew, int nE)
{
    int e = blockIdx.x * blockDim.x + threadIdx.x;
    if (e >= nE) return;
    int p = atomicAdd(&cursor[rows[e]], 1);
    ecol[p] = cols[e];
    ew[p]   = vals[e];
}

// ---------------------------------------------------------------------------
// CSR segment-sum gathers (one block of 128 threads per destination row)
// ---------------------------------------------------------------------------
// src fp32 [M,512] -> split bf16 out, plus S[r] = sum of weights
__global__ void __launch_bounds__(128)
gather_f32_kernel(const float* __restrict__ src, const int* __restrict__ offs,
                  const int* __restrict__ ecol, const float* __restrict__ ew,
                  __nv_bfloat16* __restrict__ oh, __nv_bfloat16* __restrict__ ol,
                  float* __restrict__ S)
{
    const int r = blockIdx.x;
    const int tid = threadIdx.x;
    const int beg = offs[r], end = offs[r + 1];
    float4 acc = make_float4(0.f, 0.f, 0.f, 0.f);
    float s = 0.f;
    for (int i = beg; i < end; i++) {
        int cc = __ldg(&ecol[i]);
        float w = __ldg(&ew[i]);
        float4 v = __ldg((const float4*)(src + (long)cc * 512) + tid);
        acc.x += w * v.x; acc.y += w * v.y; acc.z += w * v.z; acc.w += w * v.w;
        s += w;
    }
    if (tid == 0) S[r] = s;
    split_store4(oh + (long)r * 512 + tid * 4, ol + (long)r * 512 + tid * 4, acc);
}

// src bf16 split pair -> split bf16 out
__global__ void __launch_bounds__(128)
gather_bf16_kernel(const __nv_bfloat16* __restrict__ sh, const __nv_bfloat16* __restrict__ sl,
                   const int* __restrict__ offs, const int* __restrict__ ecol,
                   const float* __restrict__ ew,
                   __nv_bfloat16* __restrict__ oh, __nv_bfloat16* __restrict__ ol)
{
    const int r = blockIdx.x;
    const int tid = threadIdx.x;
    const int beg = offs[r], end = offs[r + 1];
    float4 acc = make_float4(0.f, 0.f, 0.f, 0.f);
    for (int i = beg; i < end; i++) {
        int cc = __ldg(&ecol[i]);
        float w = __ldg(&ew[i]);
        const __nv_bfloat162* ph = (const __nv_bfloat162*)(sh + (long)cc * 512) + tid * 2;
        const __nv_bfloat162* pl = (const __nv_bfloat162*)(sl + (long)cc * 512) + tid * 2;
        __nv_bfloat162 h0 = __ldg(ph), h1 = __ldg(ph + 1);
        __nv_bfloat162 l0 = __ldg(pl), l1 = __ldg(pl + 1);
        acc.x += w * (__bfloat162float(h0.x) + __bfloat162float(l0.x));
        acc.y += w * (__bfloat162float(h0.y) + __bfloat162float(l0.y));
        acc.z += w * (__bfloat162float(h1.x) + __bfloat162float(l1.x));
        acc.w += w * (__bfloat162float(h1.y) + __bfloat162float(l1.y));
    }
    split_store4(oh + (long)r * 512 + tid * 4, ol + (long)r * 512 + tid * 4, acc);
}

// ---------------------------------------------------------------------------
// small kernels
// ---------------------------------------------------------------------------
// W [512/1024,512] fp32 -> first 512 rows transposed/split to [512,512] bf16
__global__ void split_wT_kernel(const float* __restrict__ W,
                                __nv_bfloat16* __restrict__ wh,
                                __nv_bfloat16* __restrict__ wl)
{
    long idx = (long)blockIdx.x * blockDim.x + threadIdx.x;
    if (idx >= 512 * 512) return;
    int n = (int)(idx >> 9);
    int k = (int)(idx & 511);
    float x = __ldg(&W[(long)k * 512 + n]);
    __nv_bfloat16 h, l;
    split1(x, h, l);
    wh[idx] = h; wl[idx] = l;
}

// rt[g,n] = sum_k relu(x[root_g,k]) * W2[(512+k),n]
__global__ void root_term_kernel(const float* __restrict__ feat,
                                 const int* __restrict__ root_idx,
                                 const float* __restrict__ W2,
                                 float* __restrict__ rt)
{
    int g = blockIdx.y;
    int n = blockIdx.x * blockDim.x + threadIdx.x;
    const float* v = feat + (long)root_idx[g] * DFEAT;
    float acc = 0.f;
    const float* Wb = W2 + (long)512 * 512 + n;
#pragma unroll 4
    for (int k = 0; k < 512; k++)
        acc += fmaxf(__ldg(v + k), 0.f) * __ldg(Wb + (long)k * 512);
    rt[g * DFEAT + n] = acc;
}

// rt2[g,n] = bl[n] + sum_k h1root[g,k] * Wl[(512+k),n]
__global__ void root_term2_kernel(const float* __restrict__ h1root,
                                  const float* __restrict__ Wl,
                                  const float* __restrict__ bl,
                                  float* __restrict__ rt2)
{
    int g = blockIdx.y;
    int n = blockIdx.x * blockDim.x + threadIdx.x;
    const float* v = h1root + g * DFEAT;
    float acc = bl[n];
    const float* Wb = Wl + (long)512 * 512 + n;
#pragma unroll 4
    for (int k = 0; k < 512; k++)
        acc += __ldg(v + k) * __ldg(Wb + (long)k * 512);
    rt2[g * DFEAT + n] = acc;
}

// ---------------------------------------------------------------------------
// launch
// ---------------------------------------------------------------------------
extern "C" void kernel_launch(void* const* d_in, const int* in_sizes, int n_in,
                              void* d_out, int out_size)
{
    const float* features = (const float*)d_in[0];
    const int*   adjs     = (const int*)  d_in[1];
    const float* values   = (const float*)d_in[2];
    const int*   root_idx = (const int*)  d_in[3];
    const float* W1 = (const float*)d_in[6];
    const float* b1 = (const float*)d_in[7];
    const float* W2 = (const float*)d_in[8];
    const float* b2 = (const float*)d_in[9];
    const float* Wl = (const float*)d_in[10];
    const float* bl = (const float*)d_in[11];
    float* out = (float*)d_out;

    const int nE = in_sizes[2];

    float *S, *rt, *rt2, *h1root, *ew;
    int *cnt, *offs, *cursor, *ecol;
    __nv_bfloat16 *ah, *al, *bh, *blo, *w1h, *w1l, *w2h, *w2l, *wlh, *wll;
    cudaGetSymbolAddress((void**)&S,      g_S);
    cudaGetSymbolAddress((void**)&rt,     g_rt);
    cudaGetSymbolAddress((void**)&rt2,    g_rt2);
    cudaGetSymbolAddress((void**)&h1root, g_h1root);
    cudaGetSymbolAddress((void**)&cnt,    g_cnt);
    cudaGetSymbolAddress((void**)&offs,   g_offs);
    cudaGetSymbolAddress((void**)&cursor, g_cursor);
    cudaGetSymbolAddress((void**)&ecol,   g_ecol);
    cudaGetSymbolAddress((void**)&ew,     g_ew);
    cudaGetSymbolAddress((void**)&ah,  g_ah);
    cudaGetSymbolAddress((void**)&al,  g_al);
    cudaGetSymbolAddress((void**)&bh,  g_bh);
    cudaGetSymbolAddress((void**)&blo, g_bl);
    cudaGetSymbolAddress((void**)&w1h, g_w1h);
    cudaGetSymbolAddress((void**)&w1l, g_w1l);
    cudaGetSymbolAddress((void**)&w2h, g_w2h);
    cudaGetSymbolAddress((void**)&w2l, g_w2l);
    cudaGetSymbolAddress((void**)&wlh, g_wlh);
    cudaGetSymbolAddress((void**)&wll, g_wll);

    const int* rows = adjs;
    const int* cols = adjs + nE;

    cudaFuncSetAttribute(gemm_bf16x3<3>, cudaFuncAttributeMaxDynamicSharedMemorySize, SMTOTAL);
    cudaFuncSetAttribute(gemm_bf16x3<4>, cudaFuncAttributeMaxDynamicSharedMemorySize, SMTOTAL);
    cudaFuncSetAttribute(gemm_bf16x3<2>, cudaFuncAttributeMaxDynamicSharedMemorySize, SMTOTAL);

    dim3 ggrid(DFEAT / BN2, MROWS / BM2);             // (2, 512)
    dim3 rt_grid(2, NGRAPH);

    // --- weight splits + CSR build ---
    split_wT_kernel<<<(512 * 512 + 255) / 256, 256>>>(W1, w1h, w1l);
    split_wT_kernel<<<(512 * 512 + 255) / 256, 256>>>(W2, w2h, w2l);
    split_wT_kernel<<<(512 * 512 + 255) / 256, 256>>>(Wl, wlh, wll);
    zero_cnt_kernel<<<(MROWS + 255) / 256, 256>>>(cnt);
    hist_kernel<<<(nE + 255) / 256, 256>>>(rows, cnt, nE);
    scan_kernel<<<1, 1024>>>(cnt, offs, cursor);
    fill_csr_kernel<<<(nE + 255) / 256, 256>>>(rows, cols, values, cursor, ecol, ew, nE);
    // rt[g] = relu(x[root_g]) @ W2b
    root_term_kernel<<<rt_grid, 256>>>(features, root_idx, W2, rt);

    // --- 1) PX = P @ X  (split bf16), S row sums ---
    gather_f32_kernel<<<MROWS, 128>>>(features, offs, ecol, ew, ah, al, S);
    // --- 2) h1 = PX @ W1 + b1; epilogue: root-store, relu, split -> bh/bl ---
    gemm_bf16x3<3><<<ggrid, 512, SMTOTAL>>>(ah, al, w1h, w1l, nullptr,
                                            bh, blo, b1, nullptr, nullptr, root_idx, h1root);
    // --- 3) rt2[g] = bl + h1root @ Wlb ---
    root_term2_kernel<<<rt_grid, 256>>>(h1root, Wl, bl, rt2);
    // --- 4) Y = P @ relu(h1)  (split bf16) ---
    gather_bf16_kernel<<<MROWS, 128>>>(bh, blo, offs, ecol, ew, ah, al);
    // --- 5) h2 = Y @ W2a + b2 + S*rt[g]; relu; split -> bh/bl ---
    gemm_bf16x3<4><<<ggrid, 512, SMTOTAL>>>(ah, al, w2h, w2l, nullptr,
                                            bh, blo, b2, rt, S, nullptr, nullptr);
    // --- 6) out = leaky_relu(relu(h2) @ Wla + rt2[g]) ---
    gemm_bf16x3<2><<<ggrid, 512, SMTOTAL>>>(bh, blo, wlh, wll, out,
                                            nullptr, nullptr, nullptr, rt2, nullptr, nullptr, nullptr);
}

// round 6
// speedup vs baseline: 3.1805x; 1.1021x over previous
#include <cuda_runtime.h>
#include <cuda_bf16.h>
#include <cstdint>

#define MROWS   65536
#define DFEAT   512
#define NEDGES  65536
#define NGRAPH  16
#define GSHIFT  12          // rows per graph = 4096

// ---------------------------------------------------------------------------
// Scratch (__device__ globals; allocation-free)
// ---------------------------------------------------------------------------
__device__ float g_S[MROWS];
__device__ float g_rt[NGRAPH * DFEAT];             // relu(x[root]) @ W2b
__device__ float g_rt2[NGRAPH * DFEAT];            // bl + h1[root] @ Wlb
__device__ float g_h1root[NGRAPH * DFEAT];
__device__ __nv_bfloat16 g_ah[(size_t)MROWS * DFEAT], g_al[(size_t)MROWS * DFEAT];
__device__ __nv_bfloat16 g_bh[(size_t)MROWS * DFEAT], g_bl[(size_t)MROWS * DFEAT];
__device__ __nv_bfloat16 g_w1h[512 * 512], g_w1l[512 * 512];
__device__ __nv_bfloat16 g_w2h[512 * 512], g_w2l[512 * 512];
__device__ __nv_bfloat16 g_wlh[512 * 512], g_wll[512 * 512];
// CSR
__device__ int   g_cnt[MROWS];
__device__ int   g_offs[MROWS + 1];
__device__ int   g_cursor[MROWS];
__device__ int   g_ecol[NEDGES];
__device__ float g_ew[NEDGES];

// ---------------------------------------------------------------------------
// PTX helpers
// ---------------------------------------------------------------------------
__device__ __forceinline__ uint32_t smem_u32(const void* p) {
    return (uint32_t)__cvta_generic_to_shared(p);
}
__device__ __forceinline__ void cp_async16(uint32_t dst, const void* src) {
    asm volatile("cp.async.cg.shared.global [%0], [%1], 16;" :: "r"(dst), "l"(src));
}
__device__ __forceinline__ void cp_commit() {
    asm volatile("cp.async.commit_group;");
}
template<int N>
__device__ __forceinline__ void cp_wait() {
    asm volatile("cp.async.wait_group %0;" :: "n"(N));
}
__device__ __forceinline__ void ldsm_x4(uint32_t& r0, uint32_t& r1,
                                        uint32_t& r2, uint32_t& r3, uint32_t a) {
    asm volatile("ldmatrix.sync.aligned.m8n8.x4.shared.b16 {%0,%1,%2,%3}, [%4];"
                 : "=r"(r0), "=r"(r1), "=r"(r2), "=r"(r3) : "r"(a));
}
__device__ __forceinline__ void mma16816(float* c, const uint32_t* a, const uint32_t* b) {
    asm volatile(
        "mma.sync.aligned.m16n8k16.row.col.f32.bf16.bf16.f32 "
        "{%0,%1,%2,%3}, {%4,%5,%6,%7}, {%8,%9}, {%0,%1,%2,%3};"
        : "+f"(c[0]), "+f"(c[1]), "+f"(c[2]), "+f"(c[3])
        : "r"(a[0]), "r"(a[1]), "r"(a[2]), "r"(a[3]), "r"(b[0]), "r"(b[1]));
}

// ---------------------------------------------------------------------------
// split helpers
// ---------------------------------------------------------------------------
__device__ __forceinline__ void split1(float x, __nv_bfloat16& h, __nv_bfloat16& l) {
    h = __float2bfloat16_rn(x);
    l = __float2bfloat16_rn(x - __bfloat162float(h));
}
__device__ __forceinline__ void split_store2(__nv_bfloat16* ph, __nv_bfloat16* pl, float2 v) {
    __nv_bfloat16 h0, l0, h1, l1;
    split1(v.x, h0, l0); split1(v.y, h1, l1);
    __nv_bfloat162 hh, ll;
    hh.x = h0; hh.y = h1; ll.x = l0; ll.y = l1;
    *(__nv_bfloat162*)ph = hh; *(__nv_bfloat162*)pl = ll;
}
__device__ __forceinline__ void split_store4(__nv_bfloat16* ph, __nv_bfloat16* pl, float4 v) {
    split_store2(ph,     pl,     make_float2(v.x, v.y));
    split_store2(ph + 2, pl + 2, make_float2(v.z, v.w));
}

// ---------------------------------------------------------------------------
// bf16x3 split GEMM: C = (Ah+Al)[M,512] @ (Bh+Bl)[512,512]^T
// EPI=3: +bias(col); fp32 root-row store; relu; split->Oh/Ol
// EPI=4: +bias(col)+S[row]*rt[g,col]; relu; split->Oh/Ol
// EPI=2: +rt2[g,col]; leaky_relu; fp32 store -> C
// ---------------------------------------------------------------------------
#define BM2 128
#define BN2 256
#define NSTAGE 4
#define SMA (BM2 * 128)
#define SMB (BN2 * 128)
#define SMSTAGE (SMA + SMB)
#define SMTOTAL (NSTAGE * SMSTAGE + 1024)

template<int EPI>
__global__ void __launch_bounds__(512, 1)
gemm_bf16x3(const __nv_bfloat16* __restrict__ Ah, const __nv_bfloat16* __restrict__ Al,
            const __nv_bfloat16* __restrict__ Bh, const __nv_bfloat16* __restrict__ Bl,
            float* __restrict__ C,
            __nv_bfloat16* __restrict__ Oh, __nv_bfloat16* __restrict__ Ol,
            const float* __restrict__ bias, const float* __restrict__ rt,
            const float* __restrict__ S, const int* __restrict__ root_idx,
            float* __restrict__ h1root)
{
    constexpr int K = 512;
    extern __shared__ char dsm[];
    uint32_t sb = (smem_u32(dsm) + 1023) & ~1023u;

    const int tid  = threadIdx.x;
    const int lane = tid & 31;
    const int wid  = tid >> 5;
    const int wm   = wid & 3;
    const int wn   = wid >> 2;
    const long bm  = (long)blockIdx.y * BM2;
    const long bn  = (long)blockIdx.x * BN2;

    const __nv_bfloat16* Aseg[3] = {Ah, Ah, Al};
    const __nv_bfloat16* Bseg[3] = {Bh, Bl, Bh};
    const int cps = K >> 6;            // 8
    const int nch = 3 * cps;           // 24

    float c[2][8][4];
#pragma unroll
    for (int i = 0; i < 2; i++)
#pragma unroll
        for (int j = 0; j < 8; j++)
#pragma unroll
            for (int q = 0; q < 4; q++) c[i][j][q] = 0.0f;

    const int amat  = lane >> 3;
    const int arow0 = wm * 32 + (amat & 1) * 8 + (lane & 7);
    const int ahalf = amat >> 1;
    const int bg    = lane >> 3;
    const int bhalf = bg & 1;
    const int bn0   = wn * 64 + ((bg >> 1) << 3) + (lane & 7);

    auto loads = [&](int ch, int s) {
        int seg = (ch >= 2 * cps) ? 2 : ((ch >= cps) ? 1 : 0);
        int kk  = (ch - seg * cps) << 6;
        const __nv_bfloat16* Ab = Aseg[seg] + bm * K + kk;
        const __nv_bfloat16* Bb = Bseg[seg] + bn * K + kk;
        uint32_t As = sb + s * SMSTAGE;
        uint32_t Bs = As + SMA;
#pragma unroll
        for (int i = 0; i < 2; i++) {
            int lin = tid * 2 + i;
            int r = lin >> 3, cc = lin & 7;
            cp_async16(As + r * 128 + ((cc ^ (r & 7)) << 4), Ab + (long)r * K + cc * 8);
        }
#pragma unroll
        for (int i = 0; i < 4; i++) {
            int lin = tid * 4 + i;
            int r = lin >> 3, cc = lin & 7;
            cp_async16(Bs + r * 128 + ((cc ^ (r & 7)) << 4), Bb + (long)r * K + cc * 8);
        }
    };

    loads(0, 0); cp_commit();
    loads(1, 1); cp_commit();
    loads(2, 2); cp_commit();

    for (int k = 0; k < nch; k++) {
        cp_wait<2>();
        __syncthreads();
        if (k + 3 < nch) loads(k + 3, (k + 3) & (NSTAGE - 1));
        cp_commit();

        uint32_t As = sb + (k & (NSTAGE - 1)) * SMSTAGE;
        uint32_t Bs = As + SMA;
#pragma unroll
        for (int t = 0; t < 4; t++) {
            uint32_t a[2][4];
#pragma unroll
            for (int mi = 0; mi < 2; mi++) {
                int row = arow0 + mi * 16;
                uint32_t addr = As + row * 128 + ((((2 * t) + ahalf) ^ (row & 7)) << 4);
                ldsm_x4(a[mi][0], a[mi][1], a[mi][2], a[mi][3], addr);
            }
            uint32_t b[8][2];
#pragma unroll
            for (int j = 0; j < 4; j++) {
                int n = bn0 + j * 16;
                uint32_t addr = Bs + n * 128 + ((((2 * t) + bhalf) ^ (n & 7)) << 4);
                ldsm_x4(b[2 * j][0], b[2 * j][1], b[2 * j + 1][0], b[2 * j + 1][1], addr);
            }
#pragma unroll
            for (int mi = 0; mi < 2; mi++)
#pragma unroll
                for (int nj = 0; nj < 8; nj++)
                    mma16816(c[mi][nj], a[mi], b[nj]);
        }
    }

#pragma unroll
    for (int mi = 0; mi < 2; mi++) {
        long row = bm + wm * 32 + mi * 16 + (lane >> 2);
        int g = (int)(row >> GSHIFT);
#pragma unroll
        for (int nj = 0; nj < 8; nj++) {
            int col = (int)bn + wn * 64 + nj * 8 + 2 * (lane & 3);
            float2 v0 = {c[mi][nj][0], c[mi][nj][1]};   // row
            float2 v1 = {c[mi][nj][2], c[mi][nj][3]};   // row + 8

            if (EPI == 3) {
                float b0 = bias[col], b1v = bias[col + 1];
                v0.x += b0; v0.y += b1v; v1.x += b0; v1.y += b1v;
                int rr = root_idx[g];
                if ((long)rr == row) {
                    h1root[g * 512 + col] = v0.x; h1root[g * 512 + col + 1] = v0.y;
                }
                if ((long)rr == row + 8) {
                    h1root[g * 512 + col] = v1.x; h1root[g * 512 + col + 1] = v1.y;
                }
                v0.x = fmaxf(v0.x, 0.f); v0.y = fmaxf(v0.y, 0.f);
                v1.x = fmaxf(v1.x, 0.f); v1.y = fmaxf(v1.y, 0.f);
                split_store2(Oh + row * 512 + col,       Ol + row * 512 + col,       v0);
                split_store2(Oh + (row + 8) * 512 + col, Ol + (row + 8) * 512 + col, v1);
            } else if (EPI == 4) {
                float s0 = S[row], s1 = S[row + 8];
                float r0 = rt[g * 512 + col], r1 = rt[g * 512 + col + 1];
                float b0 = bias[col], b1v = bias[col + 1];
                v0.x += b0 + s0 * r0; v0.y += b1v + s0 * r1;
                v1.x += b0 + s1 * r0; v1.y += b1v + s1 * r1;
                v0.x = fmaxf(v0.x, 0.f); v0.y = fmaxf(v0.y, 0.f);
                v1.x = fmaxf(v1.x, 0.f); v1.y = fmaxf(v1.y, 0.f);
                split_store2(Oh + row * 512 + col,       Ol + row * 512 + col,       v0);
                split_store2(Oh + (row + 8) * 512 + col, Ol + (row + 8) * 512 + col, v1);
            } else {  // EPI == 2
                float b0 = rt[g * 512 + col], b1v = rt[g * 512 + col + 1];
                v0.x += b0; v0.y += b1v; v1.x += b0; v1.y += b1v;
                v0.x = (v0.x >= 0.f) ? v0.x : 0.01f * v0.x;
                v0.y = (v0.y >= 0.f) ? v0.y : 0.01f * v0.y;
                v1.x = (v1.x >= 0.f) ? v1.x : 0.01f * v1.x;
                v1.y = (v1.y >= 0.f) ? v1.y : 0.01f * v1.y;
                *(float2*)(C + row * 512 + col)       = v0;
                *(float2*)(C + (row + 8) * 512 + col) = v1;
            }
        }
    }
}

// ---------------------------------------------------------------------------
// fused: split+transpose W1/W2a/Wla to bf16 hi/lo AND zero the CSR histogram
// ---------------------------------------------------------------------------
__global__ void split_w_zero_kernel(const float* __restrict__ W1,
                                    const float* __restrict__ W2,
                                    const float* __restrict__ Wl,
                                    __nv_bfloat16* __restrict__ w1h, __nv_bfloat16* __restrict__ w1l,
                                    __nv_bfloat16* __restrict__ w2h, __nv_bfloat16* __restrict__ w2l,
                                    __nv_bfloat16* __restrict__ wlh, __nv_bfloat16* __restrict__ wll,
                                    int* __restrict__ cnt)
{
    long idx = (long)blockIdx.x * blockDim.x + threadIdx.x;   // 0 .. 3*512*512-1
    if (idx < MROWS) cnt[idx] = 0;
    int which = (int)(idx >> 18);            // 512*512 = 2^18
    int loc   = (int)(idx & 0x3FFFF);
    int n = loc >> 9;
    int k = loc & 511;
    const float* W = (which == 0) ? W1 : (which == 1) ? W2 : Wl;
    __nv_bfloat16* wh = (which == 0) ? w1h : (which == 1) ? w2h : wlh;
    __nv_bfloat16* wl = (which == 0) ? w1l : (which == 1) ? w2l : wll;
    float x = __ldg(&W[(long)k * 512 + n]);
    __nv_bfloat16 h, l;
    split1(x, h, l);
    wh[loc] = h; wl[loc] = l;
}

// ---------------------------------------------------------------------------
// CSR build
// ---------------------------------------------------------------------------
__global__ void hist_kernel(const int* __restrict__ rows, int* __restrict__ cnt, int nE)
{
    int e = blockIdx.x * blockDim.x + threadIdx.x;
    if (e < nE) atomicAdd(&cnt[rows[e]], 1);
}
__global__ void __launch_bounds__(1024, 1)
scan_kernel(const int* __restrict__ cnt, int* __restrict__ offs, int* __restrict__ cursor)
{
    __shared__ int ts[1024];
    const int tid = threadIdx.x;
    const int base = tid * 64;
    int local = 0;
#pragma unroll 8
    for (int i = 0; i < 64; i++) local += cnt[base + i];
    int x = local;
    ts[tid] = x; __syncthreads();
    for (int s = 1; s < 1024; s <<= 1) {
        int v = (tid >= s) ? ts[tid - s] : 0;
        __syncthreads();
        x += v; ts[tid] = x; __syncthreads();
    }
    int run = x - local;
    for (int i = 0; i < 64; i++) {
        int cc = cnt[base + i];
        offs[base + i] = run;
        cursor[base + i] = run;
        run += cc;
    }
    if (tid == 1023) offs[MROWS] = run;
}
__global__ void fill_csr_kernel(const int* __restrict__ rows, const int* __restrict__ cols,
                                const float* __restrict__ vals, int* __restrict__ cursor,
                                int* __restrict__ ecol, float* __restrict__ ew, int nE)
{
    int e = blockIdx.x * blockDim.x + threadIdx.x;
    if (e >= nE) return;
    int p = atomicAdd(&cursor[rows[e]], 1);
    ecol[p] = cols[e];
    ew[p]   = vals[e];
}

// ---------------------------------------------------------------------------
// CSR gathers (one 128-thread block per destination row), 4-edge batching
// ---------------------------------------------------------------------------
__global__ void __launch_bounds__(128)
gather_f32_kernel(const float* __restrict__ src, const int* __restrict__ offs,
                  const int* __restrict__ ecol, const float* __restrict__ ew,
                  __nv_bfloat16* __restrict__ oh, __nv_bfloat16* __restrict__ ol,
                  float* __restrict__ S)
{
    const int r = blockIdx.x;
    const int tid = threadIdx.x;
    const int beg = __ldg(&offs[r]), end = __ldg(&offs[r + 1]);
    float4 acc = make_float4(0.f, 0.f, 0.f, 0.f);
    float s = 0.f;
    int i = beg;
    for (; i + 4 <= end; i += 4) {
        int c0 = __ldg(&ecol[i]),   c1 = __ldg(&ecol[i+1]);
        int c2 = __ldg(&ecol[i+2]), c3 = __ldg(&ecol[i+3]);
        float w0 = __ldg(&ew[i]),   w1 = __ldg(&ew[i+1]);
        float w2 = __ldg(&ew[i+2]), w3 = __ldg(&ew[i+3]);
        float4 v0 = __ldg((const float4*)(src + (long)c0 * 512) + tid);
        float4 v1 = __ldg((const float4*)(src + (long)c1 * 512) + tid);
        float4 v2 = __ldg((const float4*)(src + (long)c2 * 512) + tid);
        float4 v3 = __ldg((const float4*)(src + (long)c3 * 512) + tid);
        acc.x += w0*v0.x + w1*v1.x + w2*v2.x + w3*v3.x;
        acc.y += w0*v0.y + w1*v1.y + w2*v2.y + w3*v3.y;
        acc.z += w0*v0.z + w1*v1.z + w2*v2.z + w3*v3.z;
        acc.w += w0*v0.w + w1*v1.w + w2*v2.w + w3*v3.w;
        s += w0 + w1 + w2 + w3;
    }
    for (; i < end; i++) {
        int cc = __ldg(&ecol[i]);
        float w = __ldg(&ew[i]);
        float4 v = __ldg((const float4*)(src + (long)cc * 512) + tid);
        acc.x += w * v.x; acc.y += w * v.y; acc.z += w * v.z; acc.w += w * v.w;
        s += w;
    }
    if (tid == 0) S[r] = s;
    split_store4(oh + (long)r * 512 + tid * 4, ol + (long)r * 512 + tid * 4, acc);
}

__device__ __forceinline__ float4 ld_bf16pair(const __nv_bfloat16* sh,
                                              const __nv_bfloat16* sl,
                                              long row, int tid)
{
    const __nv_bfloat162* ph = (const __nv_bfloat162*)(sh + row * 512) + tid * 2;
    const __nv_bfloat162* pl = (const __nv_bfloat162*)(sl + row * 512) + tid * 2;
    __nv_bfloat162 h0 = __ldg(ph), h1 = __ldg(ph + 1);
    __nv_bfloat162 l0 = __ldg(pl), l1 = __ldg(pl + 1);
    float4 v;
    v.x = __bfloat162float(h0.x) + __bfloat162float(l0.x);
    v.y = __bfloat162float(h0.y) + __bfloat162float(l0.y);
    v.z = __bfloat162float(h1.x) + __bfloat162float(l1.x);
    v.w = __bfloat162float(h1.y) + __bfloat162float(l1.y);
    return v;
}

__global__ void __launch_bounds__(128)
gather_bf16_kernel(const __nv_bfloat16* __restrict__ sh, const __nv_bfloat16* __restrict__ sl,
                   const int* __restrict__ offs, const int* __restrict__ ecol,
                   const float* __restrict__ ew,
                   __nv_bfloat16* __restrict__ oh, __nv_bfloat16* __restrict__ ol)
{
    const int r = blockIdx.x;
    const int tid = threadIdx.x;
    const int beg = __ldg(&offs[r]), end = __ldg(&offs[r + 1]);
    float4 acc = make_float4(0.f, 0.f, 0.f, 0.f);
    int i = beg;
    for (; i + 4 <= end; i += 4) {
        int c0 = __ldg(&ecol[i]),   c1 = __ldg(&ecol[i+1]);
        int c2 = __ldg(&ecol[i+2]), c3 = __ldg(&ecol[i+3]);
        float w0 = __ldg(&ew[i]),   w1 = __ldg(&ew[i+1]);
        float w2 = __ldg(&ew[i+2]), w3 = __ldg(&ew[i+3]);
        float4 v0 = ld_bf16pair(sh, sl, c0, tid);
        float4 v1 = ld_bf16pair(sh, sl, c1, tid);
        float4 v2 = ld_bf16pair(sh, sl, c2, tid);
        float4 v3 = ld_bf16pair(sh, sl, c3, tid);
        acc.x += w0*v0.x + w1*v1.x + w2*v2.x + w3*v3.x;
        acc.y += w0*v0.y + w1*v1.y + w2*v2.y + w3*v3.y;
        acc.z += w0*v0.z + w1*v1.z + w2*v2.z + w3*v3.z;
        acc.w += w0*v0.w + w1*v1.w + w2*v2.w + w3*v3.w;
    }
    for (; i < end; i++) {
        int cc = __ldg(&ecol[i]);
        float w = __ldg(&ew[i]);
        float4 v = ld_bf16pair(sh, sl, cc, tid);
        acc.x += w * v.x; acc.y += w * v.y; acc.z += w * v.z; acc.w += w * v.w;
    }
    split_store4(oh + (long)r * 512 + tid * 4, ol + (long)r * 512 + tid * 4, acc);
}

// ---------------------------------------------------------------------------
// root terms (parallel over k-chunks, atomic accumulate)
// ---------------------------------------------------------------------------
// rt = 0 ; rt2[g,n] = bl[n]
__global__ void init_rt_kernel(float* __restrict__ rt, float* __restrict__ rt2,
                               const float* __restrict__ bl)
{
    int idx = blockIdx.x * blockDim.x + threadIdx.x;   // 0..NGRAPH*512-1
    if (idx >= NGRAPH * DFEAT) return;
    rt[idx] = 0.f;
    rt2[idx] = bl[idx & 511];
}
// rt[g,n] += sum_{k in chunk} relu(feat[root_g,k]) * W2[(512+k),n]
__global__ void __launch_bounds__(512)
root_term_kernel(const float* __restrict__ feat, const int* __restrict__ root_idx,
                 const float* __restrict__ W2, float* __restrict__ rt)
{
    int g  = blockIdx.x;
    int kc = blockIdx.y << 6;
    int n  = threadIdx.x;
    const float* v  = feat + (long)root_idx[g] * DFEAT + kc;
    const float* Wb = W2 + (long)(512 + kc) * 512 + n;
    float acc = 0.f;
#pragma unroll 8
    for (int k = 0; k < 64; k++)
        acc += fmaxf(__ldg(v + k), 0.f) * __ldg(Wb + (long)k * 512);
    atomicAdd(&rt[g * DFEAT + n], acc);
}
// rt2[g,n] += sum_{k in chunk} h1root[g,k] * Wl[(512+k),n]
__global__ void __launch_bounds__(512)
root_term2_kernel(const float* __restrict__ h1root, const float* __restrict__ Wl,
                  float* __restrict__ rt2)
{
    int g  = blockIdx.x;
    int kc = blockIdx.y << 6;
    int n  = threadIdx.x;
    const float* v  = h1root + g * DFEAT + kc;
    const float* Wb = Wl + (long)(512 + kc) * 512 + n;
    float acc = 0.f;
#pragma unroll 8
    for (int k = 0; k < 64; k++)
        acc += __ldg(v + k) * __ldg(Wb + (long)k * 512);
    atomicAdd(&rt2[g * DFEAT + n], acc);
}

// ---------------------------------------------------------------------------
// launch  (order chosen so launch index 5 == gemm1 for ncu -s 5 -c 1)
// ---------------------------------------------------------------------------
extern "C" void kernel_launch(void* const* d_in, const int* in_sizes, int n_in,
                              void* d_out, int out_size)
{
    const float* features = (const float*)d_in[0];
    const int*   adjs     = (const int*)  d_in[1];
    const float* values   = (const float*)d_in[2];
    const int*   root_idx = (const int*)  d_in[3];
    const float* W1 = (const float*)d_in[6];
    const float* b1 = (const float*)d_in[7];
    const float* W2 = (const float*)d_in[8];
    const float* b2 = (const float*)d_in[9];
    const float* Wl = (const float*)d_in[10];
    const float* bl = (const float*)d_in[11];
    float* out = (float*)d_out;

    const int nE = in_sizes[2];

    float *S, *rt, *rt2, *h1root, *ew;
    int *cnt, *offs, *cursor, *ecol;
    __nv_bfloat16 *ah, *al, *bh, *blo, *w1h, *w1l, *w2h, *w2l, *wlh, *wll;
    cudaGetSymbolAddress((void**)&S,      g_S);
    cudaGetSymbolAddress((void**)&rt,     g_rt);
    cudaGetSymbolAddress((void**)&rt2,    g_rt2);
    cudaGetSymbolAddress((void**)&h1root, g_h1root);
    cudaGetSymbolAddress((void**)&cnt,    g_cnt);
    cudaGetSymbolAddress((void**)&offs,   g_offs);
    cudaGetSymbolAddress((void**)&cursor, g_cursor);
    cudaGetSymbolAddress((void**)&ecol,   g_ecol);
    cudaGetSymbolAddress((void**)&ew,     g_ew);
    cudaGetSymbolAddress((void**)&ah,  g_ah);
    cudaGetSymbolAddress((void**)&al,  g_al);
    cudaGetSymbolAddress((void**)&bh,  g_bh);
    cudaGetSymbolAddress((void**)&blo, g_bl);
    cudaGetSymbolAddress((void**)&w1h, g_w1h);
    cudaGetSymbolAddress((void**)&w1l, g_w1l);
    cudaGetSymbolAddress((void**)&w2h, g_w2h);
    cudaGetSymbolAddress((void**)&w2l, g_w2l);
    cudaGetSymbolAddress((void**)&wlh, g_wlh);
    cudaGetSymbolAddress((void**)&wll, g_wll);

    const int* rows = adjs;
    const int* cols = adjs + nE;

    cudaFuncSetAttribute(gemm_bf16x3<3>, cudaFuncAttributeMaxDynamicSharedMemorySize, SMTOTAL);
    cudaFuncSetAttribute(gemm_bf16x3<4>, cudaFuncAttributeMaxDynamicSharedMemorySize, SMTOTAL);
    cudaFuncSetAttribute(gemm_bf16x3<2>, cudaFuncAttributeMaxDynamicSharedMemorySize, SMTOTAL);

    dim3 ggrid(DFEAT / BN2, MROWS / BM2);             // (2, 512)
    dim3 rtg(NGRAPH, 8);

    // #0: weight split + cnt zero
    split_w_zero_kernel<<<(3 * 512 * 512 + 255) / 256, 256>>>(
        W1, W2, Wl, w1h, w1l, w2h, w2l, wlh, wll, cnt);
    // #1-3: CSR build
    hist_kernel<<<(nE + 255) / 256, 256>>>(rows, cnt, nE);
    scan_kernel<<<1, 1024>>>(cnt, offs, cursor);
    fill_csr_kernel<<<(nE + 255) / 256, 256>>>(rows, cols, values, cursor, ecol, ew, nE);
    // #4: PX = P @ X (split bf16) + S
    gather_f32_kernel<<<MROWS, 128>>>(features, offs, ecol, ew, ah, al, S);
    // #5: h1 = PX @ W1 + b1 (root-store, relu, split)       <-- ncu target
    gemm_bf16x3<3><<<ggrid, 512, SMTOTAL>>>(ah, al, w1h, w1l, nullptr,
                                            bh, blo, b1, nullptr, nullptr, root_idx, h1root);
    // #6-8: root terms
    init_rt_kernel<<<(NGRAPH * DFEAT + 255) / 256, 256>>>(rt, rt2, bl);
    root_term_kernel<<<rtg, 512>>>(features, root_idx, W2, rt);
    root_term2_kernel<<<rtg, 512>>>(h1root, Wl, rt2);
    // #9: Y = P @ relu(h1) (split bf16)
    gather_bf16_kernel<<<MROWS, 128>>>(bh, blo, offs, ecol, ew, ah, al);
    // #10: h2 = Y @ W2a + b2 + S*rt[g] (relu, split)
    gemm_bf16x3<4><<<ggrid, 512, SMTOTAL>>>(ah, al, w2h, w2l, nullptr,
                                            bh, blo, b2, rt, S, nullptr, nullptr);
    // #11: out = leaky_relu(relu(h2) @ Wla + rt2[g])
    gemm_bf16x3<2><<<ggrid, 512, SMTOTAL>>>(bh, blo, wlh, wll, out,
                                            nullptr, nullptr, nullptr, rt2, nullptr, nullptr, nullptr);
}